// round 1
// baseline (speedup 1.0000x reference)
#include <cuda_runtime.h>
#include <math.h>

#define L_SEQ 256
#define NB    4
#define H     12
#define HD    64
#define E     768
#define FF    3072
#define NTOK  (L_SEQ * NB)   // 1024

// ---------------- scratch (device globals; no allocation) ----------------
__device__ float g_q[NB*H*L_SEQ*HD];       // (n,h,l,d), pre-scaled by 1/8
__device__ float g_k[NB*H*L_SEQ*HD];       // (n,h,l,d)
__device__ float g_vT[NB*H*HD*L_SEQ];      // (n,h,d,l)
__device__ float g_qp[NB*H*L_SEQ*HD];      // (n,h,i,c)  q @ p_w slice
__device__ float g_qb[NB*H*L_SEQ];         // q . p_b
__device__ float g_scores[NB*H*L_SEQ*L_SEQ];
__device__ float g_ctx[NTOK*E];            // (l,n,e)
__device__ float g_attnout[NTOK*E];
__device__ float g_x1[NTOK*E];
__device__ float g_ff1[NTOK*FF];
__device__ float g_ff2[NTOK*E];

enum { M_PLAIN = 0, M_GELU = 1, M_Q = 2, M_K = 3, M_VT = 4, M_CTX = 5 };

// ---------------- generic tiled GEMM: C = (A @ B^T + bias) * alpha -------
// A: [M,K] row-major, B: [N,K] row-major. 64x64 tile, K-chunks of 16.
__global__ void gemm64(const float* __restrict__ A, const float* __restrict__ B,
                       const float* __restrict__ bias, float* __restrict__ C,
                       int M, int N, int K, long sA, long sB, long sC,
                       int mode, float alpha)
{
    __shared__ float As[16][65];
    __shared__ float Bs[16][65];
    const int bz = blockIdx.z;
    A += (long)bz * sA;
    B += (long)bz * sB;
    const int tid = threadIdx.x;          // 256 threads
    const int tx = tid & 15, ty = tid >> 4;
    const int row0 = blockIdx.y * 64, col0 = blockIdx.x * 64;

    float acc[4][4];
#pragma unroll
    for (int i = 0; i < 4; i++)
#pragma unroll
        for (int j = 0; j < 4; j++) acc[i][j] = 0.f;

    for (int k0 = 0; k0 < K; k0 += 16) {
#pragma unroll
        for (int e = tid; e < 1024; e += 256) {
            int r = e >> 4, kk = e & 15;
            int gr = row0 + r;
            As[kk][r] = (gr < M) ? A[(long)gr * K + k0 + kk] : 0.f;
        }
#pragma unroll
        for (int e = tid; e < 1024; e += 256) {
            int r = e >> 4, kk = e & 15;
            int gc = col0 + r;
            Bs[kk][r] = (gc < N) ? B[(long)gc * K + k0 + kk] : 0.f;
        }
        __syncthreads();
#pragma unroll
        for (int kk = 0; kk < 16; kk++) {
            float a[4], b[4];
#pragma unroll
            for (int u = 0; u < 4; u++) a[u] = As[kk][ty * 4 + u];
#pragma unroll
            for (int u = 0; u < 4; u++) b[u] = Bs[kk][tx * 4 + u];
#pragma unroll
            for (int i = 0; i < 4; i++)
#pragma unroll
                for (int j = 0; j < 4; j++) acc[i][j] += a[i] * b[j];
        }
        __syncthreads();
    }

#pragma unroll
    for (int i = 0; i < 4; i++) {
#pragma unroll
        for (int j = 0; j < 4; j++) {
            int gm = row0 + ty * 4 + i;
            int gn = col0 + tx * 4 + j;
            if (gm >= M || gn >= N) continue;
            float v = acc[i][j];
            if (bias) v += bias[gn];
            v *= alpha;
            long idx;
            switch (mode) {
                case M_GELU:
                    v = 0.5f * v * (1.0f + erff(v * 0.70710678118654752f));
                    // fallthrough to plain index
                case M_PLAIN:
                    idx = (long)bz * sC + (long)gm * N + gn;
                    break;
                case M_Q:
                case M_K: {
                    int nb = gm & 3, l = gm >> 2;
                    int hh = gn >> 6, d = gn & 63;
                    idx = (((long)(nb * H + hh)) * L_SEQ + l) * HD + d;
                    break;
                }
                case M_VT: {
                    int nb = gm & 3, l = gm >> 2;
                    int hh = gn >> 6, d = gn & 63;
                    idx = (((long)(nb * H + hh)) * HD + d) * L_SEQ + l;
                    break;
                }
                default: { // M_CTX: batch bz = n*H+h, gm = i (seq), gn = d
                    int nb = bz / H, hh = bz % H;
                    idx = ((long)gm * NB + nb) * E + hh * HD + gn;
                    break;
                }
            }
            C[idx] = v;
        }
    }
}

// ---------------- qp[n,h,i,c] = sum_d q[n,h,i,d] * p_w[h*64+d, c] --------
__global__ void qp_kernel(const float* __restrict__ p_w, const float* __restrict__ p_b)
{
    const int b = blockIdx.x;            // (n*H + h)*L + i
    const int hh = (b / L_SEQ) % H;
    const long base = (long)b * HD;
    __shared__ float qrow[64];
    const int c = threadIdx.x;           // 64 threads
    qrow[c] = g_q[base + c];
    __syncthreads();
    float s = 0.f;
#pragma unroll
    for (int d = 0; d < 64; d++)
        s += qrow[d] * p_w[(hh * 64 + d) * 64 + c];
    g_qp[base + c] = s;
    if (c == 0) {
        float sb = 0.f;
#pragma unroll
        for (int d = 0; d < 64; d++) sb += qrow[d] * p_b[hh * 64 + d];
        g_qb[b] = sb;
    }
}

// ---- scores[n,h,i,j] += sum_c qp[n,h,i,c]*pos[n,i,j,c] + qb[n,h,i] ------
__global__ void cp_kernel(const float* __restrict__ pos)
{
    const int b = blockIdx.x;            // n*L + i
    const int n = b / L_SEQ, i = b % L_SEQ;
    const int j = threadIdx.x;           // 256 threads
    __shared__ float qps[H * 64];
    __shared__ float qbs[H];
    for (int e = j; e < H * 64; e += 256) {
        int hh = e >> 6, c = e & 63;
        qps[e] = g_qp[(((long)n * H + hh) * L_SEQ + i) * HD + c];
    }
    if (j < H) qbs[j] = g_qb[((long)n * H + j) * L_SEQ + i];
    __syncthreads();

    const float4* pr = (const float4*)(pos + ((((long)n * L_SEQ + i) * L_SEQ) + j) * 64);
    float s[H];
#pragma unroll
    for (int hh = 0; hh < H; hh++) s[hh] = 0.f;
#pragma unroll
    for (int cc = 0; cc < 16; cc++) {
        float4 pv = pr[cc];
#pragma unroll
        for (int hh = 0; hh < H; hh++) {
            const float* qh = &qps[hh * 64 + cc * 4];
            s[hh] += qh[0] * pv.x + qh[1] * pv.y + qh[2] * pv.z + qh[3] * pv.w;
        }
    }
#pragma unroll
    for (int hh = 0; hh < H; hh++) {
        long idx = ((((long)n * H + hh) * L_SEQ + i) * L_SEQ) + j;
        g_scores[idx] += s[hh] + qbs[hh];
    }
}

// ---------------- row softmax over last dim (256) ------------------------
__global__ void softmax_kernel()
{
    const long row = blockIdx.x;
    const int j = threadIdx.x;
    __shared__ float red[8];
    float x = g_scores[row * L_SEQ + j];
    float m = x;
#pragma unroll
    for (int o = 16; o > 0; o >>= 1) m = fmaxf(m, __shfl_xor_sync(0xffffffffu, m, o));
    if ((j & 31) == 0) red[j >> 5] = m;
    __syncthreads();
    if (j < 32) {
        float t = (j < 8) ? red[j] : -1e30f;
#pragma unroll
        for (int o = 4; o > 0; o >>= 1) t = fmaxf(t, __shfl_xor_sync(0xffffffffu, t, o));
        if (j == 0) red[0] = t;
    }
    __syncthreads();
    m = red[0];
    float e = __expf(x - m);
    float s = e;
#pragma unroll
    for (int o = 16; o > 0; o >>= 1) s += __shfl_xor_sync(0xffffffffu, s, o);
    __syncthreads();
    if ((j & 31) == 0) red[j >> 5] = s;
    __syncthreads();
    if (j < 32) {
        float t = (j < 8) ? red[j] : 0.f;
#pragma unroll
        for (int o = 4; o > 0; o >>= 1) t += __shfl_xor_sync(0xffffffffu, t, o);
        if (j == 0) red[0] = t;
    }
    __syncthreads();
    g_scores[row * L_SEQ + j] = e / red[0];
}

// ---------------- out = LayerNorm(a + b) * gamma + beta ------------------
__global__ void ln_kernel(const float* __restrict__ a, const float* __restrict__ b,
                          const float* __restrict__ gamma, const float* __restrict__ beta,
                          float* __restrict__ out)
{
    const int row = blockIdx.x;          // 1024
    const int t = threadIdx.x;           // 256
    __shared__ float rs[8], rq[8];
    float v[3];
    float s = 0.f, s2 = 0.f;
#pragma unroll
    for (int u = 0; u < 3; u++) {
        long idx = (long)row * E + t + u * 256;
        float x = a[idx] + b[idx];
        v[u] = x; s += x; s2 += x * x;
    }
#pragma unroll
    for (int o = 16; o > 0; o >>= 1) {
        s  += __shfl_xor_sync(0xffffffffu, s, o);
        s2 += __shfl_xor_sync(0xffffffffu, s2, o);
    }
    if ((t & 31) == 0) { rs[t >> 5] = s; rq[t >> 5] = s2; }
    __syncthreads();
    if (t < 32) {
        float a1 = (t < 8) ? rs[t] : 0.f;
        float a2 = (t < 8) ? rq[t] : 0.f;
#pragma unroll
        for (int o = 4; o > 0; o >>= 1) {
            a1 += __shfl_xor_sync(0xffffffffu, a1, o);
            a2 += __shfl_xor_sync(0xffffffffu, a2, o);
        }
        if (t == 0) { rs[0] = a1; rq[0] = a2; }
    }
    __syncthreads();
    float mean = rs[0] * (1.f / 768.f);
    float var  = rq[0] * (1.f / 768.f) - mean * mean;
    float r = rsqrtf(var + 1e-5f);
#pragma unroll
    for (int u = 0; u < 3; u++) {
        int c = t + u * 256;
        out[(long)row * E + c] = (v[u] - mean) * r * gamma[c] + beta[c];
    }
}

// ---------------- host launcher ------------------------------------------
extern "C" void kernel_launch(void* const* d_in, const int* in_sizes, int n_in,
                              void* d_out, int out_size)
{
    const float* src    = (const float*)d_in[0];
    const float* pos    = (const float*)d_in[1];
    const float* q_w    = (const float*)d_in[2];
    const float* q_b    = (const float*)d_in[3];
    const float* k_w    = (const float*)d_in[4];
    const float* k_b    = (const float*)d_in[5];
    const float* v_w    = (const float*)d_in[6];
    const float* v_b    = (const float*)d_in[7];
    const float* p_w    = (const float*)d_in[8];
    const float* p_b    = (const float*)d_in[9];
    const float* out_w  = (const float*)d_in[10];
    const float* out_b  = (const float*)d_in[11];
    const float* lin1_w = (const float*)d_in[12];
    const float* lin1_b = (const float*)d_in[13];
    const float* lin2_w = (const float*)d_in[14];
    const float* lin2_b = (const float*)d_in[15];
    const float* n1_g   = (const float*)d_in[16];
    const float* n1_b   = (const float*)d_in[17];
    const float* n2_g   = (const float*)d_in[18];
    const float* n2_b   = (const float*)d_in[19];
    float* out = (float*)d_out;

    float *pq, *pk, *pvT, *pscores, *pctx, *pattn, *px1, *pff1, *pff2;
    cudaGetSymbolAddress((void**)&pq,      g_q);
    cudaGetSymbolAddress((void**)&pk,      g_k);
    cudaGetSymbolAddress((void**)&pvT,     g_vT);
    cudaGetSymbolAddress((void**)&pscores, g_scores);
    cudaGetSymbolAddress((void**)&pctx,    g_ctx);
    cudaGetSymbolAddress((void**)&pattn,   g_attnout);
    cudaGetSymbolAddress((void**)&px1,     g_x1);
    cudaGetSymbolAddress((void**)&pff1,    g_ff1);
    cudaGetSymbolAddress((void**)&pff2,    g_ff2);

    const float scaling = 0.125f;   // 64^-0.5

    // Q, K, V projections (write into attention-friendly layouts)
    gemm64<<<dim3(E / 64, NTOK / 64, 1), 256>>>(src, q_w, q_b, pq,  NTOK, E, E, 0, 0, 0, M_Q,  scaling);
    gemm64<<<dim3(E / 64, NTOK / 64, 1), 256>>>(src, k_w, k_b, pk,  NTOK, E, E, 0, 0, 0, M_K,  1.f);
    gemm64<<<dim3(E / 64, NTOK / 64, 1), 256>>>(src, v_w, v_b, pvT, NTOK, E, E, 0, 0, 0, M_VT, 1.f);

    // qp = q @ p_w (per-head slice), qb = q . p_b
    qp_kernel<<<NB * H * L_SEQ, 64>>>(p_w, p_b);

    // content-content scores: q @ k^T (batched over n,h)
    gemm64<<<dim3(4, 4, NB * H), 256>>>(pq, pk, nullptr, pscores,
                                        L_SEQ, L_SEQ, HD,
                                        (long)L_SEQ * HD, (long)L_SEQ * HD, (long)L_SEQ * L_SEQ,
                                        M_PLAIN, 1.f);

    // + content-position scores (reads pos exactly once)
    cp_kernel<<<NB * L_SEQ, 256>>>(pos);

    softmax_kernel<<<NB * H * L_SEQ, 256>>>();

    // ctx = attn @ v  (v stored transposed), scattered to (L,N,E)
    gemm64<<<dim3(1, 4, NB * H), 256>>>(pscores, pvT, nullptr, pctx,
                                        L_SEQ, HD, L_SEQ,
                                        (long)L_SEQ * L_SEQ, (long)HD * L_SEQ, 0,
                                        M_CTX, 1.f);

    // output projection
    gemm64<<<dim3(E / 64, NTOK / 64, 1), 256>>>(pctx, out_w, out_b, pattn, NTOK, E, E, 0, 0, 0, M_PLAIN, 1.f);

    // x1 = LN(src + attn_out)
    ln_kernel<<<NTOK, 256>>>(src, pattn, n1_g, n1_b, px1);

    // FFN
    gemm64<<<dim3(FF / 64, NTOK / 64, 1), 256>>>(px1, lin1_w, lin1_b, pff1, NTOK, FF, E, 0, 0, 0, M_GELU, 1.f);
    gemm64<<<dim3(E / 64, NTOK / 64, 1), 256>>>(pff1, lin2_w, lin2_b, pff2, NTOK, E, FF, 0, 0, 0, M_PLAIN, 1.f);

    // out = LN(x1 + ff)
    ln_kernel<<<NTOK, 256>>>(px1, pff2, n2_g, n2_b, out);
}

// round 5
// speedup vs baseline: 3.7724x; 3.7724x over previous
#include <cuda_runtime.h>
#include <cuda_bf16.h>
#include <math.h>
#include <stdint.h>

#define L_SEQ 256
#define NB    4
#define H     12
#define HD    64
#define E     768
#define FF    3072
#define NTOK  (L_SEQ * NB)   // 1024

// ---------------- fp32 scratch ----------------
__device__ float g_q[NB*H*L_SEQ*HD];       // (n,h,l,d), pre-scaled by 1/8
__device__ float g_k[NB*H*L_SEQ*HD];       // (n,h,l,d)
__device__ float g_vT[NB*H*HD*L_SEQ];      // (n,h,d,l)
__device__ float g_qp[NB*H*L_SEQ*HD];
__device__ float g_qb[NB*H*L_SEQ];
__device__ float g_scores[NB*H*L_SEQ*L_SEQ];
__device__ float g_ctx[NTOK*E];
__device__ float g_attnout[2*NTOK*E];      // 2 split-K partials
__device__ float g_x1[NTOK*E];
__device__ float g_ff2[4*NTOK*E];          // 4 split-K partials

// ---------------- bf16 hi/lo split scratch ----------------
__device__ __align__(16) __nv_bfloat16 g_src_h[NTOK*E],  g_src_l[NTOK*E];
__device__ __align__(16) __nv_bfloat16 g_x1_h[NTOK*E],   g_x1_l[NTOK*E];
__device__ __align__(16) __nv_bfloat16 g_ff1_h[NTOK*FF], g_ff1_l[NTOK*FF];
__device__ __align__(16) __nv_bfloat16 g_ctx_h[NTOK*E],  g_ctx_l[NTOK*E];
__device__ __align__(16) __nv_bfloat16 g_wqkv_h[3*E*E],  g_wqkv_l[3*E*E];
__device__ __align__(16) __nv_bfloat16 g_wout_h[E*E],    g_wout_l[E*E];
__device__ __align__(16) __nv_bfloat16 g_w1_h[FF*E],     g_w1_l[FF*E];
__device__ __align__(16) __nv_bfloat16 g_w2_h[E*FF],     g_w2_l[E*FF];

// =================== PTX helpers (sm_80-compatible only) ===================
__device__ __forceinline__ uint32_t smem_u32(const void* p) {
    uint32_t a;
    asm("{ .reg .u64 t; cvta.to.shared.u64 t, %1; cvt.u32.u64 %0, t; }" : "=r"(a) : "l"(p));
    return a;
}
__device__ __forceinline__ void cp16(uint32_t dst, const void* src) {
    asm volatile("cp.async.cg.shared.global [%0], [%1], 16;\n" :: "r"(dst), "l"(src));
}
__device__ __forceinline__ void ldm4(uint32_t* r, uint32_t a) {
    asm volatile("ldmatrix.sync.aligned.m8n8.x4.shared.b16 {%0,%1,%2,%3}, [%4];"
                 : "=r"(r[0]), "=r"(r[1]), "=r"(r[2]), "=r"(r[3]) : "r"(a));
}
__device__ __forceinline__ void mma16816(float* d, const uint32_t* a, uint32_t b0, uint32_t b1) {
    asm volatile(
        "mma.sync.aligned.m16n8k16.row.col.f32.bf16.bf16.f32 "
        "{%0,%1,%2,%3}, {%4,%5,%6,%7}, {%8,%9}, {%0,%1,%2,%3};"
        : "+f"(d[0]), "+f"(d[1]), "+f"(d[2]), "+f"(d[3])
        : "r"(a[0]), "r"(a[1]), "r"(a[2]), "r"(a[3]), "r"(b0), "r"(b1));
}

// =================== fp32 -> bf16 hi/lo split ===================
__global__ void cvt4(const float4* __restrict__ in, __nv_bfloat162* __restrict__ h,
                     __nv_bfloat162* __restrict__ l, int n4)
{
    int i = blockIdx.x * blockDim.x + threadIdx.x;
    if (i >= n4) return;
    float4 x = in[i];
    __nv_bfloat16 h0 = __float2bfloat16(x.x), h1 = __float2bfloat16(x.y);
    __nv_bfloat16 h2 = __float2bfloat16(x.z), h3 = __float2bfloat16(x.w);
    __nv_bfloat16 l0 = __float2bfloat16(x.x - __bfloat162float(h0));
    __nv_bfloat16 l1 = __float2bfloat16(x.y - __bfloat162float(h1));
    __nv_bfloat16 l2 = __float2bfloat16(x.z - __bfloat162float(h2));
    __nv_bfloat16 l3 = __float2bfloat16(x.w - __bfloat162float(h3));
    h[2*i]   = __nv_bfloat162(h0, h1);
    h[2*i+1] = __nv_bfloat162(h2, h3);
    l[2*i]   = __nv_bfloat162(l0, l1);
    l[2*i+1] = __nv_bfloat162(l2, l3);
}

// =================== tensor-core GEMM (mma.sync): C = A @ B^T + bias ======
// A[M,K], B[N,K] hi/lo bf16 split. 128x128 CTA tile, BK=32, 8 warps (32x64),
// double-buffered cp.async. Split-K via blockIdx.z (klen per split).
// mode 0: fp32 -> C + z*M*N (bias only on z==0)
// mode 2: QKV scatter -> g_q/g_k/g_vT (b0,b1,b2 = q_b,k_b,v_b)
// mode 3: bias+GELU -> bf16 hi/lo (Ch, Cl)
#define SA 40                           // smem row stride, elements
#define TILE_BYTES (128 * SA * 2)       // 10240
#define STAGE_BYTES (4 * TILE_BYTES)    // 40960
#define OFF_AH 0
#define OFF_AL (1 * TILE_BYTES)
#define OFF_BH (2 * TILE_BYTES)
#define OFF_BL (3 * TILE_BYTES)
#define SM_TOTAL (2 * STAGE_BYTES)      // 81920

__global__ void __launch_bounds__(256, 1) tgemm(
    const __nv_bfloat16* __restrict__ Ah, const __nv_bfloat16* __restrict__ Al,
    const __nv_bfloat16* __restrict__ Bh, const __nv_bfloat16* __restrict__ Bl,
    const float* __restrict__ b0, const float* __restrict__ b1, const float* __restrict__ b2,
    float* __restrict__ C, __nv_bfloat16* __restrict__ Ch, __nv_bfloat16* __restrict__ Cl,
    int M, int N, int K, int klen, int mode)
{
    extern __shared__ char smem[];
    const uint32_t sb = smem_u32(smem);
    const int tid = threadIdx.x;
    const int lane = tid & 31, wid = tid >> 5;
    const int wm = wid & 3, wn = wid >> 2;            // 4 warps in M, 2 in N
    const int row0 = blockIdx.y * 128, col0 = blockIdx.x * 128;
    const int kz = blockIdx.z;
    const int koff = kz * klen;

    float acc[2][8][4];
#pragma unroll
    for (int i = 0; i < 2; i++)
#pragma unroll
        for (int j = 0; j < 8; j++)
#pragma unroll
            for (int r = 0; r < 4; r++) acc[i][j][r] = 0.f;

    const int niter = klen >> 5;

    auto load = [&](int it, int s) {
#pragma unroll
        for (int u = 0; u < 2; u++) {
            int e = tid + u * 256;                    // 0..511
            int r = e >> 2, c = e & 3;                // row, 16B chunk
            uint32_t so = sb + s * STAGE_BYTES + (uint32_t)((r * SA + c * 8) * 2);
            long gA = (long)(row0 + r) * K + koff + it * 32 + c * 8;
            long gB = (long)(col0 + r) * K + koff + it * 32 + c * 8;
            cp16(so + OFF_AH, Ah + gA);
            cp16(so + OFF_AL, Al + gA);
            cp16(so + OFF_BH, Bh + gB);
            cp16(so + OFF_BL, Bl + gB);
        }
        asm volatile("cp.async.commit_group;" ::: "memory");
    };

    auto compute = [&](int s) {
        const uint32_t base = sb + s * STAGE_BYTES;
#pragma unroll
        for (int ks = 0; ks < 2; ks++) {
            const uint32_t kcol = (uint32_t)((ks * 16 + (lane >> 4) * 8) * 2);
            uint32_t ah[2][4], al[2][4];
            const uint32_t arow = (uint32_t)(wm * 32 + (lane & 15));
#pragma unroll
            for (int t = 0; t < 2; t++) {
                uint32_t off = ((arow + t * 16) * SA) * 2 + kcol;
                ldm4(ah[t], base + OFF_AH + off);
                ldm4(al[t], base + OFF_AL + off);
            }
            uint32_t bh[4][4], bl[4][4];
            const uint32_t brow = (uint32_t)(wn * 64 + (lane & 15));
#pragma unroll
            for (int u = 0; u < 4; u++) {
                uint32_t off = ((brow + u * 16) * SA) * 2 + kcol;
                ldm4(bh[u], base + OFF_BH + off);
                ldm4(bl[u], base + OFF_BL + off);
            }
#pragma unroll
            for (int mt = 0; mt < 2; mt++)
#pragma unroll
                for (int nt = 0; nt < 8; nt++) {
                    int u = nt >> 1, p = nt & 1;
                    mma16816(acc[mt][nt], ah[mt], bh[u][p], bh[u][p + 2]);
                    mma16816(acc[mt][nt], ah[mt], bl[u][p], bl[u][p + 2]);
                    mma16816(acc[mt][nt], al[mt], bh[u][p], bh[u][p + 2]);
                }
        }
    };

    load(0, 0);
    for (int it = 0; it < niter; it++) {
        if (it + 1 < niter) {
            load(it + 1, (it + 1) & 1);
            asm volatile("cp.async.wait_group 1;" ::: "memory");
        } else {
            asm volatile("cp.async.wait_group 0;" ::: "memory");
        }
        __syncthreads();
        compute(it & 1);
        __syncthreads();
    }

    // ---- epilogue from register accumulators ----
    const int rl = lane >> 2, cl = (lane & 3) * 2;
#pragma unroll
    for (int mt = 0; mt < 2; mt++) {
#pragma unroll
        for (int g = 0; g < 2; g++) {
            const int m = row0 + wm * 32 + mt * 16 + g * 8 + rl;
#pragma unroll
            for (int nt = 0; nt < 8; nt++) {
                const int n = col0 + wn * 64 + nt * 8 + cl;
                float v0 = acc[mt][nt][2 * g];
                float v1 = acc[mt][nt][2 * g + 1];
                if (mode == 0) {
                    if (b0 && kz == 0) { v0 += b0[n]; v1 += b0[n + 1]; }
                    float2 o = make_float2(v0, v1);
                    *(float2*)(C + (long)kz * M * N + (long)m * N + n) = o;
                } else if (mode == 3) {
                    v0 += b0[n]; v1 += b0[n + 1];
                    v0 = 0.5f * v0 * (1.0f + erff(v0 * 0.70710678118654752f));
                    v1 = 0.5f * v1 * (1.0f + erff(v1 * 0.70710678118654752f));
                    __nv_bfloat16 h0 = __float2bfloat16(v0), h1 = __float2bfloat16(v1);
                    __nv_bfloat16 l0 = __float2bfloat16(v0 - __bfloat162float(h0));
                    __nv_bfloat16 l1 = __float2bfloat16(v1 - __bfloat162float(h1));
                    *(__nv_bfloat162*)(Ch + (long)m * N + n) = __nv_bfloat162(h0, h1);
                    *(__nv_bfloat162*)(Cl + (long)m * N + n) = __nv_bfloat162(l0, l1);
                } else { // mode 2: QKV scatter
                    const int l = m >> 2, nbb = m & 3;
#pragma unroll
                    for (int q = 0; q < 2; q++) {
                        int gcol = n + q;
                        float v = q ? v1 : v0;
                        int seg = gcol / E;
                        int cc = gcol - seg * E;
                        int hh = cc >> 6, dd = cc & 63;
                        if (seg == 0)
                            g_q[(((long)(nbb * H + hh)) * L_SEQ + l) * HD + dd] = (v + b0[cc]) * 0.125f;
                        else if (seg == 1)
                            g_k[(((long)(nbb * H + hh)) * L_SEQ + l) * HD + dd] = v + b1[cc];
                        else
                            g_vT[(((long)(nbb * H + hh)) * HD + dd) * L_SEQ + l] = v + b2[cc];
                    }
                }
            }
        }
    }
}

// =================== fp32 tiled GEMM (attention only) ===================
enum { M_PLAIN = 0, M_CTX = 5 };
__global__ void gemm64(const float* __restrict__ A, const float* __restrict__ B,
                       float* __restrict__ C,
                       int M, int N, int K, long sA, long sB, long sC, int mode)
{
    __shared__ float As[16][65];
    __shared__ float Bs[16][65];
    const int bz = blockIdx.z;
    A += (long)bz * sA;
    B += (long)bz * sB;
    const int tid = threadIdx.x;
    const int tx = tid & 15, ty = tid >> 4;
    const int row0 = blockIdx.y * 64, col0 = blockIdx.x * 64;

    float acc[4][4];
#pragma unroll
    for (int i = 0; i < 4; i++)
#pragma unroll
        for (int j = 0; j < 4; j++) acc[i][j] = 0.f;

    for (int k0 = 0; k0 < K; k0 += 16) {
#pragma unroll
        for (int e = tid; e < 1024; e += 256) {
            int r = e >> 4, kk = e & 15;
            int gr = row0 + r;
            As[kk][r] = (gr < M) ? A[(long)gr * K + k0 + kk] : 0.f;
        }
#pragma unroll
        for (int e = tid; e < 1024; e += 256) {
            int r = e >> 4, kk = e & 15;
            int gc = col0 + r;
            Bs[kk][r] = (gc < N) ? B[(long)gc * K + k0 + kk] : 0.f;
        }
        __syncthreads();
#pragma unroll
        for (int kk = 0; kk < 16; kk++) {
            float a[4], b[4];
#pragma unroll
            for (int u = 0; u < 4; u++) a[u] = As[kk][ty * 4 + u];
#pragma unroll
            for (int u = 0; u < 4; u++) b[u] = Bs[kk][tx * 4 + u];
#pragma unroll
            for (int i = 0; i < 4; i++)
#pragma unroll
                for (int j = 0; j < 4; j++) acc[i][j] += a[i] * b[j];
        }
        __syncthreads();
    }

#pragma unroll
    for (int i = 0; i < 4; i++) {
#pragma unroll
        for (int j = 0; j < 4; j++) {
            int gm = row0 + ty * 4 + i;
            int gn = col0 + tx * 4 + j;
            if (gm >= M || gn >= N) continue;
            float v = acc[i][j];
            long idx;
            if (mode == M_CTX) { // batch bz = n*H+h, gm = i (seq), gn = d
                int nb = bz / H, hh = bz % H;
                idx = ((long)gm * NB + nb) * E + hh * HD + gn;
            } else {
                idx = (long)bz * sC + (long)gm * N + gn;
            }
            C[idx] = v;
        }
    }
}

// ---------------- qp[n,h,i,c] = sum_d q[n,h,i,d] * p_w[h*64+d, c] --------
__global__ void qp_kernel(const float* __restrict__ p_w, const float* __restrict__ p_b)
{
    const int b = blockIdx.x;            // (n*H + h)*L + i
    const int hh = (b / L_SEQ) % H;
    const long base = (long)b * HD;
    __shared__ float qrow[64];
    const int c = threadIdx.x;           // 64 threads
    qrow[c] = g_q[base + c];
    __syncthreads();
    float s = 0.f;
#pragma unroll
    for (int d = 0; d < 64; d++)
        s += qrow[d] * p_w[(hh * 64 + d) * 64 + c];
    g_qp[base + c] = s;
    if (c == 0) {
        float sb = 0.f;
#pragma unroll
        for (int d = 0; d < 64; d++) sb += qrow[d] * p_b[hh * 64 + d];
        g_qb[b] = sb;
    }
}

// ---- scores[n,h,i,j] += sum_c qp[n,h,i,c]*pos[n,i,j,c] + qb[n,h,i] ------
__global__ void cp_kernel(const float* __restrict__ pos)
{
    const int b = blockIdx.x;            // n*L + i
    const int n = b / L_SEQ, i = b % L_SEQ;
    const int j = threadIdx.x;           // 256 threads
    __shared__ float qps[H * 64];
    __shared__ float qbs[H];
    for (int e = j; e < H * 64; e += 256) {
        int hh = e >> 6, c = e & 63;
        qps[e] = g_qp[(((long)n * H + hh) * L_SEQ + i) * HD + c];
    }
    if (j < H) qbs[j] = g_qb[((long)n * H + j) * L_SEQ + i];
    __syncthreads();

    const float4* pr = (const float4*)(pos + ((((long)n * L_SEQ + i) * L_SEQ) + j) * 64);
    float s[H];
#pragma unroll
    for (int hh = 0; hh < H; hh++) s[hh] = 0.f;
#pragma unroll
    for (int cc = 0; cc < 16; cc++) {
        float4 pv = pr[cc];
#pragma unroll
        for (int hh = 0; hh < H; hh++) {
            const float* qh = &qps[hh * 64 + cc * 4];
            s[hh] += qh[0] * pv.x + qh[1] * pv.y + qh[2] * pv.z + qh[3] * pv.w;
        }
    }
#pragma unroll
    for (int hh = 0; hh < H; hh++) {
        long idx = ((((long)n * H + hh) * L_SEQ + i) * L_SEQ) + j;
        g_scores[idx] += s[hh] + qbs[hh];
    }
}

// ---------------- row softmax over last dim (256) ------------------------
__global__ void softmax_kernel()
{
    const long row = blockIdx.x;
    const int j = threadIdx.x;
    __shared__ float red[8];
    float x = g_scores[row * L_SEQ + j];
    float m = x;
#pragma unroll
    for (int o = 16; o > 0; o >>= 1) m = fmaxf(m, __shfl_xor_sync(0xffffffffu, m, o));
    if ((j & 31) == 0) red[j >> 5] = m;
    __syncthreads();
    if (j < 32) {
        float t = (j < 8) ? red[j] : -1e30f;
#pragma unroll
        for (int o = 4; o > 0; o >>= 1) t = fmaxf(t, __shfl_xor_sync(0xffffffffu, t, o));
        if (j == 0) red[0] = t;
    }
    __syncthreads();
    m = red[0];
    float e = __expf(x - m);
    float s = e;
#pragma unroll
    for (int o = 16; o > 0; o >>= 1) s += __shfl_xor_sync(0xffffffffu, s, o);
    __syncthreads();
    if ((j & 31) == 0) red[j >> 5] = s;
    __syncthreads();
    if (j < 32) {
        float t = (j < 8) ? red[j] : 0.f;
#pragma unroll
        for (int o = 4; o > 0; o >>= 1) t += __shfl_xor_sync(0xffffffffu, t, o);
        if (j == 0) red[0] = t;
    }
    __syncthreads();
    g_scores[row * L_SEQ + j] = e / red[0];
}

// ---- out = LayerNorm(a + sum_{z<np} p[z*ps + .]) * gamma + beta ---------
__global__ void ln_multi(const float* __restrict__ a, const float* __restrict__ p,
                         int nparts, long pstride,
                         const float* __restrict__ gamma, const float* __restrict__ beta,
                         float* __restrict__ out)
{
    const int row = blockIdx.x;          // 1024
    const int t = threadIdx.x;           // 256
    __shared__ float rs[8], rq[8];
    float v[3];
    float s = 0.f, s2 = 0.f;
#pragma unroll
    for (int u = 0; u < 3; u++) {
        long idx = (long)row * E + t + u * 256;
        float x = a[idx];
        for (int z = 0; z < nparts; z++) x += p[z * pstride + idx];
        v[u] = x; s += x; s2 += x * x;
    }
#pragma unroll
    for (int o = 16; o > 0; o >>= 1) {
        s  += __shfl_xor_sync(0xffffffffu, s, o);
        s2 += __shfl_xor_sync(0xffffffffu, s2, o);
    }
    if ((t & 31) == 0) { rs[t >> 5] = s; rq[t >> 5] = s2; }
    __syncthreads();
    if (t < 32) {
        float a1 = (t < 8) ? rs[t] : 0.f;
        float a2 = (t < 8) ? rq[t] : 0.f;
#pragma unroll
        for (int o = 4; o > 0; o >>= 1) {
            a1 += __shfl_xor_sync(0xffffffffu, a1, o);
            a2 += __shfl_xor_sync(0xffffffffu, a2, o);
        }
        if (t == 0) { rs[0] = a1; rq[0] = a2; }
    }
    __syncthreads();
    float mean = rs[0] * (1.f / 768.f);
    float var  = rq[0] * (1.f / 768.f) - mean * mean;
    float r = rsqrtf(var + 1e-5f);
#pragma unroll
    for (int u = 0; u < 3; u++) {
        int c = t + u * 256;
        out[(long)row * E + c] = (v[u] - mean) * r * gamma[c] + beta[c];
    }
}

// =================== host launcher ===================
static inline void cvt_launch(const float* in, __nv_bfloat16* h, __nv_bfloat16* l, int n)
{
    int n4 = n / 4;
    cvt4<<<(n4 + 255) / 256, 256>>>((const float4*)in, (__nv_bfloat162*)h, (__nv_bfloat162*)l, n4);
}

extern "C" void kernel_launch(void* const* d_in, const int* in_sizes, int n_in,
                              void* d_out, int out_size)
{
    const float* src    = (const float*)d_in[0];
    const float* pos    = (const float*)d_in[1];
    const float* q_w    = (const float*)d_in[2];
    const float* q_b    = (const float*)d_in[3];
    const float* k_w    = (const float*)d_in[4];
    const float* k_b    = (const float*)d_in[5];
    const float* v_w    = (const float*)d_in[6];
    const float* v_b    = (const float*)d_in[7];
    const float* p_w    = (const float*)d_in[8];
    const float* p_b    = (const float*)d_in[9];
    const float* out_w  = (const float*)d_in[10];
    const float* out_b  = (const float*)d_in[11];
    const float* lin1_w = (const float*)d_in[12];
    const float* lin1_b = (const float*)d_in[13];
    const float* lin2_w = (const float*)d_in[14];
    const float* lin2_b = (const float*)d_in[15];
    const float* n1_g   = (const float*)d_in[16];
    const float* n1_b   = (const float*)d_in[17];
    const float* n2_g   = (const float*)d_in[18];
    const float* n2_b   = (const float*)d_in[19];
    float* out = (float*)d_out;

    cudaFuncSetAttribute(tgemm, cudaFuncAttributeMaxDynamicSharedMemorySize, SM_TOTAL);

    float *pq, *pk, *pvT, *pscores, *pctx, *pattn, *px1, *pff2;
    cudaGetSymbolAddress((void**)&pq,      g_q);
    cudaGetSymbolAddress((void**)&pk,      g_k);
    cudaGetSymbolAddress((void**)&pvT,     g_vT);
    cudaGetSymbolAddress((void**)&pscores, g_scores);
    cudaGetSymbolAddress((void**)&pctx,    g_ctx);
    cudaGetSymbolAddress((void**)&pattn,   g_attnout);
    cudaGetSymbolAddress((void**)&px1,     g_x1);
    cudaGetSymbolAddress((void**)&pff2,    g_ff2);

    __nv_bfloat16 *srch, *srcl, *x1h, *x1l, *ff1h, *ff1l, *ctxh, *ctxl;
    __nv_bfloat16 *wqkvh, *wqkvl, *wouth, *woutl, *w1h, *w1l, *w2h, *w2l;
    cudaGetSymbolAddress((void**)&srch,  g_src_h);  cudaGetSymbolAddress((void**)&srcl,  g_src_l);
    cudaGetSymbolAddress((void**)&x1h,   g_x1_h);   cudaGetSymbolAddress((void**)&x1l,   g_x1_l);
    cudaGetSymbolAddress((void**)&ff1h,  g_ff1_h);  cudaGetSymbolAddress((void**)&ff1l,  g_ff1_l);
    cudaGetSymbolAddress((void**)&ctxh,  g_ctx_h);  cudaGetSymbolAddress((void**)&ctxl,  g_ctx_l);
    cudaGetSymbolAddress((void**)&wqkvh, g_wqkv_h); cudaGetSymbolAddress((void**)&wqkvl, g_wqkv_l);
    cudaGetSymbolAddress((void**)&wouth, g_wout_h); cudaGetSymbolAddress((void**)&woutl, g_wout_l);
    cudaGetSymbolAddress((void**)&w1h,   g_w1_h);   cudaGetSymbolAddress((void**)&w1l,   g_w1_l);
    cudaGetSymbolAddress((void**)&w2h,   g_w2_h);   cudaGetSymbolAddress((void**)&w2l,   g_w2_l);

    // ---- weight + input splits ----
    cvt_launch(q_w,    wqkvh,           wqkvl,           E * E);
    cvt_launch(k_w,    wqkvh + E * E,   wqkvl + E * E,   E * E);
    cvt_launch(v_w,    wqkvh + 2*E*E,   wqkvl + 2*E*E,   E * E);
    cvt_launch(out_w,  wouth,           woutl,           E * E);
    cvt_launch(lin1_w, w1h,             w1l,             FF * E);
    cvt_launch(lin2_w, w2h,             w2l,             E * FF);
    cvt_launch(src,    srch,            srcl,            NTOK * E);

    // ---- fused QKV projection (tensor cores), scatter to q/k/vT layouts ----
    tgemm<<<dim3(3 * E / 128, NTOK / 128, 1), 256, SM_TOTAL>>>(
        srch, srcl, wqkvh, wqkvl, q_b, k_b, v_b,
        nullptr, nullptr, nullptr, NTOK, 3 * E, E, E, 2);

    // ---- attention scores + softmax (fp32) ----
    qp_kernel<<<NB * H * L_SEQ, 64>>>(p_w, p_b);
    gemm64<<<dim3(4, 4, NB * H), 256>>>(pq, pk, pscores,
                                        L_SEQ, L_SEQ, HD,
                                        (long)L_SEQ * HD, (long)L_SEQ * HD, (long)L_SEQ * L_SEQ,
                                        M_PLAIN);
    cp_kernel<<<NB * L_SEQ, 256>>>(pos);
    softmax_kernel<<<NB * H * L_SEQ, 256>>>();
    gemm64<<<dim3(1, 4, NB * H), 256>>>(pscores, pvT, pctx,
                                        L_SEQ, HD, L_SEQ,
                                        (long)L_SEQ * L_SEQ, (long)HD * L_SEQ, 0,
                                        M_CTX);

    // ---- output projection (tensor cores, split-K=2) ----
    cvt_launch(pctx, ctxh, ctxl, NTOK * E);
    tgemm<<<dim3(E / 128, NTOK / 128, 2), 256, SM_TOTAL>>>(
        ctxh, ctxl, wouth, woutl, out_b, nullptr, nullptr,
        pattn, nullptr, nullptr, NTOK, E, E, E / 2, 0);

    // ---- x1 = LN(src + partial0 + partial1) ----
    ln_multi<<<NTOK, 256>>>(src, pattn, 2, (long)NTOK * E, n1_g, n1_b, px1);

    // ---- FFN (tensor cores) ----
    cvt_launch(px1, x1h, x1l, NTOK * E);
    // FFN1: GELU epilogue writes bf16 hi/lo directly
    tgemm<<<dim3(FF / 128, NTOK / 128, 1), 256, SM_TOTAL>>>(
        x1h, x1l, w1h, w1l, lin1_b, nullptr, nullptr,
        nullptr, ff1h, ff1l, NTOK, FF, E, E, 3);
    // FFN2: split-K=4
    tgemm<<<dim3(E / 128, NTOK / 128, 4), 256, SM_TOTAL>>>(
        ff1h, ff1l, w2h, w2l, lin2_b, nullptr, nullptr,
        pff2, nullptr, nullptr, NTOK, E, FF, FF / 4, 0);

    // ---- out = LN(x1 + 4 partials) ----
    ln_multi<<<NTOK, 256>>>(px1, pff2, 4, (long)NTOK * E, n2_g, n2_b, out);
}

// round 6
// speedup vs baseline: 3.7759x; 1.0009x over previous
#include <cuda_runtime.h>
#include <cuda_bf16.h>
#include <math.h>
#include <stdint.h>

#define L_SEQ 256
#define NB    4
#define H     12
#define HD    64
#define E     768
#define FF    3072
#define NTOK  (L_SEQ * NB)   // 1024

// ---------------- fp32 scratch ----------------
__device__ float g_q[NB*H*L_SEQ*HD];       // (n,h,l,d), pre-scaled by 1/8
__device__ float g_k[NB*H*L_SEQ*HD];       // (n,h,l,d)
__device__ float g_vT[NB*H*HD*L_SEQ];      // (n,h,d,l)
__device__ float g_qp[NB*H*L_SEQ*HD];
__device__ float g_qb[NB*H*L_SEQ];
__device__ float g_scores[NB*H*L_SEQ*L_SEQ];
__device__ float g_ctx[NTOK*E];
__device__ float g_attnout[2*NTOK*E];      // 2 split-K partials
__device__ float g_x1[NTOK*E];
__device__ float g_ff1[NTOK*FF];
__device__ float g_ff2[4*NTOK*E];          // 4 split-K partials

// =================== PTX helpers (sm_80-compatible only) ===================
__device__ __forceinline__ uint32_t smem_u32(const void* p) {
    uint32_t a;
    asm("{ .reg .u64 t; cvta.to.shared.u64 t, %1; cvt.u32.u64 %0, t; }" : "=r"(a) : "l"(p));
    return a;
}
__device__ __forceinline__ void ldm4(uint32_t* r, uint32_t a) {
    asm volatile("ldmatrix.sync.aligned.m8n8.x4.shared.b16 {%0,%1,%2,%3}, [%4];"
                 : "=r"(r[0]), "=r"(r[1]), "=r"(r[2]), "=r"(r[3]) : "r"(a));
}
__device__ __forceinline__ void mma16816(float* d, const uint32_t* a, uint32_t b0, uint32_t b1) {
    asm volatile(
        "mma.sync.aligned.m16n8k16.row.col.f32.bf16.bf16.f32 "
        "{%0,%1,%2,%3}, {%4,%5,%6,%7}, {%8,%9}, {%0,%1,%2,%3};"
        : "+f"(d[0]), "+f"(d[1]), "+f"(d[2]), "+f"(d[3])
        : "r"(a[0]), "r"(a[1]), "r"(a[2]), "r"(a[3]), "r"(b0), "r"(b1));
}
// fp32x4 -> bf16 hi (uint2) + lo (uint2)
__device__ __forceinline__ void split4(float4 x, uint2& h, uint2& l) {
    __nv_bfloat16 h0 = __float2bfloat16(x.x), h1 = __float2bfloat16(x.y);
    __nv_bfloat16 h2 = __float2bfloat16(x.z), h3 = __float2bfloat16(x.w);
    __nv_bfloat162 hh0(h0, h1), hh1(h2, h3);
    h.x = *(uint32_t*)&hh0; h.y = *(uint32_t*)&hh1;
    __nv_bfloat162 ll0(__float2bfloat16(x.x - __bfloat162float(h0)),
                       __float2bfloat16(x.y - __bfloat162float(h1)));
    __nv_bfloat162 ll1(__float2bfloat16(x.z - __bfloat162float(h2)),
                       __float2bfloat16(x.w - __bfloat162float(h3)));
    l.x = *(uint32_t*)&ll0; l.y = *(uint32_t*)&ll1;
}

// =================== tensor-core GEMM (mma.sync, fused fp32->hi/lo) =======
// A[M,K], B[N,K] fp32. Conversion to bf16 hi/lo happens in the smem-store
// path. 128x128 CTA tile, BK=32, 8 warps (32x64 warp tile), double-buffered.
// Split-K via blockIdx.z (klen per split).
// mode 0: fp32 -> C + z*M*N (bias only on z==0)
// mode 1: bias+GELU -> C
// mode 2: QKV scatter -> g_q/g_k/g_vT (B0/B1/B2 = q_w/k_w/v_w; b0/b1/b2 biases)
#define SA 40                           // smem row stride, elements
#define TILE_BYTES (128 * SA * 2)       // 10240
#define STAGE_BYTES (4 * TILE_BYTES)    // 40960
#define OFF_AH 0
#define OFF_AL (1 * TILE_BYTES)
#define OFF_BH (2 * TILE_BYTES)
#define OFF_BL (3 * TILE_BYTES)
#define SM_TOTAL (2 * STAGE_BYTES)      // 81920

__global__ void __launch_bounds__(256, 1) tgemm(
    const float* __restrict__ A,
    const float* __restrict__ B0, const float* __restrict__ B1, const float* __restrict__ B2,
    const float* __restrict__ b0, const float* __restrict__ b1, const float* __restrict__ b2,
    float* __restrict__ C, int M, int N, int K, int klen, int mode)
{
    extern __shared__ char smem[];
    const uint32_t sb = smem_u32(smem);
    const int tid = threadIdx.x;
    const int lane = tid & 31, wid = tid >> 5;
    const int wm = wid & 3, wn = wid >> 2;            // 4 warps in M, 2 in N
    const int row0 = blockIdx.y * 128, col0 = blockIdx.x * 128;
    const int kz = blockIdx.z;
    const int koff = kz * klen;

    // B segment select (QKV mode: each 128-col CTA lies inside one 768 segment)
    const float* B = B0;
    int colb = col0;
    if (mode == 2) {
        int seg = col0 / E;
        B = (seg == 0) ? B0 : ((seg == 1) ? B1 : B2);
        colb = col0 - seg * E;
    }

    float acc[2][8][4];
#pragma unroll
    for (int i = 0; i < 2; i++)
#pragma unroll
        for (int j = 0; j < 8; j++)
#pragma unroll
            for (int r = 0; r < 4; r++) acc[i][j][r] = 0.f;

    const int niter = klen >> 5;
    float4 ra[4], rb[4];

    auto ldreg = [&](int it) {
#pragma unroll
        for (int u = 0; u < 4; u++) {
            int e = tid + u * 256;                    // 0..1023
            int r = e >> 3, c = e & 3;                // A: 128 rows x 8 float4-chunks
            int c2 = (e >> 2) & 1;
            (void)c2;
            int rr = e >> 3, cc = e & 7;
            ra[u] = *(const float4*)(A + (long)(row0 + rr) * K + koff + it * 32 + cc * 4);
            rb[u] = *(const float4*)(B + (long)(colb + rr) * K + koff + it * 32 + cc * 4);
            (void)r; (void)c;
        }
    };
    auto store_stage = [&](int s) {
        char* p = smem + s * STAGE_BYTES;
#pragma unroll
        for (int u = 0; u < 4; u++) {
            int e = tid + u * 256;
            int rr = e >> 3, cc = e & 7;
            uint32_t off = (uint32_t)((rr * SA + cc * 4) * 2);
            uint2 h, l;
            split4(ra[u], h, l);
            *(uint2*)(p + OFF_AH + off) = h;
            *(uint2*)(p + OFF_AL + off) = l;
            split4(rb[u], h, l);
            *(uint2*)(p + OFF_BH + off) = h;
            *(uint2*)(p + OFF_BL + off) = l;
        }
    };
    auto compute = [&](int s) {
        const uint32_t base = sb + s * STAGE_BYTES;
#pragma unroll
        for (int ks = 0; ks < 2; ks++) {
            const uint32_t kcol = (uint32_t)((ks * 16 + (lane >> 4) * 8) * 2);
            uint32_t ah[2][4], al[2][4];
            const uint32_t arow = (uint32_t)(wm * 32 + (lane & 15));
#pragma unroll
            for (int t = 0; t < 2; t++) {
                uint32_t off = ((arow + t * 16) * SA) * 2 + kcol;
                ldm4(ah[t], base + OFF_AH + off);
                ldm4(al[t], base + OFF_AL + off);
            }
            uint32_t bh[4][4], bl[4][4];
            const uint32_t brow = (uint32_t)(wn * 64 + (lane & 15));
#pragma unroll
            for (int u = 0; u < 4; u++) {
                uint32_t off = ((brow + u * 16) * SA) * 2 + kcol;
                ldm4(bh[u], base + OFF_BH + off);
                ldm4(bl[u], base + OFF_BL + off);
            }
#pragma unroll
            for (int mt = 0; mt < 2; mt++)
#pragma unroll
                for (int nt = 0; nt < 8; nt++) {
                    int u = nt >> 1, p = nt & 1;
                    mma16816(acc[mt][nt], ah[mt], bh[u][p], bh[u][p + 2]);
                    mma16816(acc[mt][nt], ah[mt], bl[u][p], bl[u][p + 2]);
                    mma16816(acc[mt][nt], al[mt], bh[u][p], bh[u][p + 2]);
                }
        }
    };

    ldreg(0);
    for (int it = 0; it < niter; it++) {
        const int s = it & 1;
        __syncthreads();                 // stage s free (its last readers done)
        store_stage(s);
        if (it + 1 < niter) ldreg(it + 1);   // LDG latency overlaps compute
        __syncthreads();
        compute(s);
    }

    // ---- epilogue from register accumulators ----
    const int rl = lane >> 2, cl = (lane & 3) * 2;
#pragma unroll
    for (int mt = 0; mt < 2; mt++) {
#pragma unroll
        for (int g = 0; g < 2; g++) {
            const int m = row0 + wm * 32 + mt * 16 + g * 8 + rl;
#pragma unroll
            for (int nt = 0; nt < 8; nt++) {
                const int n = col0 + wn * 64 + nt * 8 + cl;
                float v0 = acc[mt][nt][2 * g];
                float v1 = acc[mt][nt][2 * g + 1];
                if (mode == 0) {
                    if (b0 && kz == 0) { v0 += b0[n]; v1 += b0[n + 1]; }
                    *(float2*)(C + (long)kz * M * N + (long)m * N + n) = make_float2(v0, v1);
                } else if (mode == 1) {
                    v0 += b0[n]; v1 += b0[n + 1];
                    v0 = 0.5f * v0 * (1.0f + erff(v0 * 0.70710678118654752f));
                    v1 = 0.5f * v1 * (1.0f + erff(v1 * 0.70710678118654752f));
                    *(float2*)(C + (long)m * N + n) = make_float2(v0, v1);
                } else { // mode 2: QKV scatter
                    const int l = m >> 2, nbb = m & 3;
#pragma unroll
                    for (int q = 0; q < 2; q++) {
                        int gcol = n + q;
                        float v = q ? v1 : v0;
                        int seg = gcol / E;
                        int cc = gcol - seg * E;
                        int hh = cc >> 6, dd = cc & 63;
                        if (seg == 0)
                            g_q[(((long)(nbb * H + hh)) * L_SEQ + l) * HD + dd] = (v + b0[cc]) * 0.125f;
                        else if (seg == 1)
                            g_k[(((long)(nbb * H + hh)) * L_SEQ + l) * HD + dd] = v + b1[cc];
                        else
                            g_vT[(((long)(nbb * H + hh)) * HD + dd) * L_SEQ + l] = v + b2[cc];
                    }
                }
            }
        }
    }
}

// =================== fp32 tiled GEMM (attention only) ===================
enum { M_PLAIN = 0, M_CTX = 5 };
__global__ void gemm64(const float* __restrict__ A, const float* __restrict__ B,
                       float* __restrict__ C,
                       int M, int N, int K, long sA, long sB, long sC, int mode)
{
    __shared__ float As[16][65];
    __shared__ float Bs[16][65];
    const int bz = blockIdx.z;
    A += (long)bz * sA;
    B += (long)bz * sB;
    const int tid = threadIdx.x;
    const int tx = tid & 15, ty = tid >> 4;
    const int row0 = blockIdx.y * 64, col0 = blockIdx.x * 64;

    float acc[4][4];
#pragma unroll
    for (int i = 0; i < 4; i++)
#pragma unroll
        for (int j = 0; j < 4; j++) acc[i][j] = 0.f;

    for (int k0 = 0; k0 < K; k0 += 16) {
#pragma unroll
        for (int e = tid; e < 1024; e += 256) {
            int r = e >> 4, kk = e & 15;
            int gr = row0 + r;
            As[kk][r] = (gr < M) ? A[(long)gr * K + k0 + kk] : 0.f;
        }
#pragma unroll
        for (int e = tid; e < 1024; e += 256) {
            int r = e >> 4, kk = e & 15;
            int gc = col0 + r;
            Bs[kk][r] = (gc < N) ? B[(long)gc * K + k0 + kk] : 0.f;
        }
        __syncthreads();
#pragma unroll
        for (int kk = 0; kk < 16; kk++) {
            float a[4], b[4];
#pragma unroll
            for (int u = 0; u < 4; u++) a[u] = As[kk][ty * 4 + u];
#pragma unroll
            for (int u = 0; u < 4; u++) b[u] = Bs[kk][tx * 4 + u];
#pragma unroll
            for (int i = 0; i < 4; i++)
#pragma unroll
                for (int j = 0; j < 4; j++) acc[i][j] += a[i] * b[j];
        }
        __syncthreads();
    }

#pragma unroll
    for (int i = 0; i < 4; i++) {
#pragma unroll
        for (int j = 0; j < 4; j++) {
            int gm = row0 + ty * 4 + i;
            int gn = col0 + tx * 4 + j;
            if (gm >= M || gn >= N) continue;
            float v = acc[i][j];
            long idx;
            if (mode == M_CTX) { // batch bz = n*H+h, gm = i (seq), gn = d
                int nb = bz / H, hh = bz % H;
                idx = ((long)gm * NB + nb) * E + hh * HD + gn;
            } else {
                idx = (long)bz * sC + (long)gm * N + gn;
            }
            C[idx] = v;
        }
    }
}

// ---- qp[n,h,i,c] = sum_d q[n,h,i,d]*p_w[h*64+d,c]; qb = q . p_b ---------
// grid (16, 12): 64-row tile over (n*L), per head. p_w slice loaded once.
__global__ void qp2_kernel(const float* __restrict__ p_w, const float* __restrict__ p_b)
{
    const int h = blockIdx.y;
    const int m0 = blockIdx.x * 64;
    __shared__ float w[64][65];
    __shared__ float qs[64][65];
    __shared__ float pb[64];
    const int tid = threadIdx.x;          // 256
    for (int e = tid; e < 4096; e += 256) {
        int d = e >> 6, c = e & 63;
        w[d][c] = p_w[(h * 64 + d) * 64 + c];
    }
    if (tid < 64) pb[tid] = p_b[h * 64 + tid];
    for (int e = tid; e < 4096; e += 256) {
        int r = e >> 6, d = e & 63;
        int mg = m0 + r;
        int n = mg >> 8, l = mg & 255;
        qs[r][d] = g_q[(((long)(n * H + h)) * L_SEQ + l) * HD + d];
    }
    __syncthreads();

    const int rr = tid >> 2, cg = tid & 3;   // row, 16-col group
    float acc[16];
#pragma unroll
    for (int c = 0; c < 16; c++) acc[c] = 0.f;
#pragma unroll
    for (int d = 0; d < 64; d++) {
        float qv = qs[rr][d];
#pragma unroll
        for (int c = 0; c < 16; c++) acc[c] += qv * w[d][cg * 16 + c];
    }
    const int mg = m0 + rr;
    const int n = mg >> 8, l = mg & 255;
    const long base = (((long)(n * H + h)) * L_SEQ + l) * HD;
#pragma unroll
    for (int c = 0; c < 16; c++) g_qp[base + cg * 16 + c] = acc[c];
    if (cg == 0) {
        float sb = 0.f;
#pragma unroll
        for (int d = 0; d < 64; d++) sb += qs[rr][d] * pb[d];
        g_qb[((long)n * H + h) * L_SEQ + l] = sb;
    }
}

// ---- scores[n,h,i,j] += sum_c qp[n,h,i,c]*pos[n,i,j,c] + qb[n,h,i] ------
__global__ void cp_kernel(const float* __restrict__ pos)
{
    const int b = blockIdx.x;            // n*L + i
    const int n = b / L_SEQ, i = b % L_SEQ;
    const int j = threadIdx.x;           // 256 threads
    __shared__ float qps[H * 64];
    __shared__ float qbs[H];
    for (int e = j; e < H * 64; e += 256) {
        int hh = e >> 6, c = e & 63;
        qps[e] = g_qp[(((long)n * H + hh) * L_SEQ + i) * HD + c];
    }
    if (j < H) qbs[j] = g_qb[((long)n * H + j) * L_SEQ + i];
    __syncthreads();

    const float4* pr = (const float4*)(pos + ((((long)n * L_SEQ + i) * L_SEQ) + j) * 64);
    float s[H];
#pragma unroll
    for (int hh = 0; hh < H; hh++) s[hh] = 0.f;
#pragma unroll
    for (int cc = 0; cc < 16; cc++) {
        float4 pv = pr[cc];
#pragma unroll
        for (int hh = 0; hh < H; hh++) {
            const float* qh = &qps[hh * 64 + cc * 4];
            s[hh] += qh[0] * pv.x + qh[1] * pv.y + qh[2] * pv.z + qh[3] * pv.w;
        }
    }
#pragma unroll
    for (int hh = 0; hh < H; hh++) {
        long idx = ((((long)n * H + hh) * L_SEQ + i) * L_SEQ) + j;
        g_scores[idx] += s[hh] + qbs[hh];
    }
}

// ---------------- row softmax over last dim (256) ------------------------
__global__ void softmax_kernel()
{
    const long row = blockIdx.x;
    const int j = threadIdx.x;
    __shared__ float red[8];
    float x = g_scores[row * L_SEQ + j];
    float m = x;
#pragma unroll
    for (int o = 16; o > 0; o >>= 1) m = fmaxf(m, __shfl_xor_sync(0xffffffffu, m, o));
    if ((j & 31) == 0) red[j >> 5] = m;
    __syncthreads();
    if (j < 32) {
        float t = (j < 8) ? red[j] : -1e30f;
#pragma unroll
        for (int o = 4; o > 0; o >>= 1) t = fmaxf(t, __shfl_xor_sync(0xffffffffu, t, o));
        if (j == 0) red[0] = t;
    }
    __syncthreads();
    m = red[0];
    float e = __expf(x - m);
    float s = e;
#pragma unroll
    for (int o = 16; o > 0; o >>= 1) s += __shfl_xor_sync(0xffffffffu, s, o);
    __syncthreads();
    if ((j & 31) == 0) red[j >> 5] = s;
    __syncthreads();
    if (j < 32) {
        float t = (j < 8) ? red[j] : 0.f;
#pragma unroll
        for (int o = 4; o > 0; o >>= 1) t += __shfl_xor_sync(0xffffffffu, t, o);
        if (j == 0) red[0] = t;
    }
    __syncthreads();
    g_scores[row * L_SEQ + j] = e / red[0];
}

// ---- out = LayerNorm(a + sum_{z<np} p[z*ps + .]) * gamma + beta ---------
__global__ void ln_multi(const float* __restrict__ a, const float* __restrict__ p,
                         int nparts, long pstride,
                         const float* __restrict__ gamma, const float* __restrict__ beta,
                         float* __restrict__ out)
{
    const int row = blockIdx.x;          // 1024
    const int t = threadIdx.x;           // 256
    __shared__ float rs[8], rq[8];
    float v[3];
    float s = 0.f, s2 = 0.f;
#pragma unroll
    for (int u = 0; u < 3; u++) {
        long idx = (long)row * E + t + u * 256;
        float x = a[idx];
        for (int z = 0; z < nparts; z++) x += p[z * pstride + idx];
        v[u] = x; s += x; s2 += x * x;
    }
#pragma unroll
    for (int o = 16; o > 0; o >>= 1) {
        s  += __shfl_xor_sync(0xffffffffu, s, o);
        s2 += __shfl_xor_sync(0xffffffffu, s2, o);
    }
    if ((t & 31) == 0) { rs[t >> 5] = s; rq[t >> 5] = s2; }
    __syncthreads();
    if (t < 32) {
        float a1 = (t < 8) ? rs[t] : 0.f;
        float a2 = (t < 8) ? rq[t] : 0.f;
#pragma unroll
        for (int o = 4; o > 0; o >>= 1) {
            a1 += __shfl_xor_sync(0xffffffffu, a1, o);
            a2 += __shfl_xor_sync(0xffffffffu, a2, o);
        }
        if (t == 0) { rs[0] = a1; rq[0] = a2; }
    }
    __syncthreads();
    float mean = rs[0] * (1.f / 768.f);
    float var  = rq[0] * (1.f / 768.f) - mean * mean;
    float r = rsqrtf(var + 1e-5f);
#pragma unroll
    for (int u = 0; u < 3; u++) {
        int c = t + u * 256;
        out[(long)row * E + c] = (v[u] - mean) * r * gamma[c] + beta[c];
    }
}

// =================== host launcher ===================
extern "C" void kernel_launch(void* const* d_in, const int* in_sizes, int n_in,
                              void* d_out, int out_size)
{
    const float* src    = (const float*)d_in[0];
    const float* pos    = (const float*)d_in[1];
    const float* q_w    = (const float*)d_in[2];
    const float* q_b    = (const float*)d_in[3];
    const float* k_w    = (const float*)d_in[4];
    const float* k_b    = (const float*)d_in[5];
    const float* v_w    = (const float*)d_in[6];
    const float* v_b    = (const float*)d_in[7];
    const float* p_w    = (const float*)d_in[8];
    const float* p_b    = (const float*)d_in[9];
    const float* out_w  = (const float*)d_in[10];
    const float* out_b  = (const float*)d_in[11];
    const float* lin1_w = (const float*)d_in[12];
    const float* lin1_b = (const float*)d_in[13];
    const float* lin2_w = (const float*)d_in[14];
    const float* lin2_b = (const float*)d_in[15];
    const float* n1_g   = (const float*)d_in[16];
    const float* n1_b   = (const float*)d_in[17];
    const float* n2_g   = (const float*)d_in[18];
    const float* n2_b   = (const float*)d_in[19];
    float* out = (float*)d_out;

    cudaFuncSetAttribute(tgemm, cudaFuncAttributeMaxDynamicSharedMemorySize, SM_TOTAL);

    float *pq, *pk, *pvT, *pscores, *pctx, *pattn, *px1, *pff1, *pff2;
    cudaGetSymbolAddress((void**)&pq,      g_q);
    cudaGetSymbolAddress((void**)&pk,      g_k);
    cudaGetSymbolAddress((void**)&pvT,     g_vT);
    cudaGetSymbolAddress((void**)&pscores, g_scores);
    cudaGetSymbolAddress((void**)&pctx,    g_ctx);
    cudaGetSymbolAddress((void**)&pattn,   g_attnout);
    cudaGetSymbolAddress((void**)&px1,     g_x1);
    cudaGetSymbolAddress((void**)&pff1,    g_ff1);
    cudaGetSymbolAddress((void**)&pff2,    g_ff2);

    // ---- fused QKV projection (fp32 in, convert-in-kernel), scatter ----
    tgemm<<<dim3(3 * E / 128, NTOK / 128, 1), 256, SM_TOTAL>>>(
        src, q_w, k_w, v_w, q_b, k_b, v_b,
        nullptr, NTOK, 3 * E, E, E, 2);

    // ---- attention scores + softmax (fp32) ----
    qp2_kernel<<<dim3(16, 12), 256>>>(p_w, p_b);
    gemm64<<<dim3(4, 4, NB * H), 256>>>(pq, pk, pscores,
                                        L_SEQ, L_SEQ, HD,
                                        (long)L_SEQ * HD, (long)L_SEQ * HD, (long)L_SEQ * L_SEQ,
                                        M_PLAIN);
    cp_kernel<<<NB * L_SEQ, 256>>>(pos);
    softmax_kernel<<<NB * H * L_SEQ, 256>>>();
    gemm64<<<dim3(1, 4, NB * H), 256>>>(pscores, pvT, pctx,
                                        L_SEQ, HD, L_SEQ,
                                        (long)L_SEQ * L_SEQ, (long)HD * L_SEQ, 0,
                                        M_CTX);

    // ---- output projection (split-K=2) ----
    tgemm<<<dim3(E / 128, NTOK / 128, 2), 256, SM_TOTAL>>>(
        pctx, out_w, nullptr, nullptr, out_b, nullptr, nullptr,
        pattn, NTOK, E, E, E / 2, 0);

    // ---- x1 = LN(src + partial0 + partial1) ----
    ln_multi<<<NTOK, 256>>>(src, pattn, 2, (long)NTOK * E, n1_g, n1_b, px1);

    // ---- FFN ----
    tgemm<<<dim3(FF / 128, NTOK / 128, 1), 256, SM_TOTAL>>>(
        px1, lin1_w, nullptr, nullptr, lin1_b, nullptr, nullptr,
        pff1, NTOK, FF, E, E, 1);
    tgemm<<<dim3(E / 128, NTOK / 128, 4), 256, SM_TOTAL>>>(
        pff1, lin2_w, nullptr, nullptr, lin2_b, nullptr, nullptr,
        pff2, NTOK, E, FF, FF / 4, 0);

    // ---- out = LN(x1 + 4 partials) ----
    ln_multi<<<NTOK, 256>>>(px1, pff2, 4, (long)NTOK * E, n2_g, n2_b, out);
}

// round 7
// speedup vs baseline: 4.1653x; 1.1031x over previous
#include <cuda_runtime.h>
#include <cuda_bf16.h>
#include <math.h>
#include <stdint.h>

#define L_SEQ 256
#define NB    4
#define H     12
#define HD    64
#define E     768
#define FF    3072
#define NTOK  (L_SEQ * NB)   // 1024
#define NHB   (NB * H)       // 48

// ---------------- fp32 scratch ----------------
__device__ float g_qp[NB*H*L_SEQ*HD];
__device__ float g_qb[NB*H*L_SEQ];
__device__ float g_scores[NB*H*L_SEQ*L_SEQ];
__device__ float g_ctx[NTOK*E];
__device__ float g_attnout[2*NTOK*E];      // 2 split-K partials
__device__ float g_x1[NTOK*E];
__device__ float g_ff1[NTOK*FF];
__device__ float g_ff2[4*NTOK*E];          // 4 split-K partials

// ---------------- bf16 hi/lo operands ----------------
__device__ __align__(16) __nv_bfloat16 g_qh[NB*H*L_SEQ*HD], g_ql[NB*H*L_SEQ*HD];   // (n,h,l,d) *0.125
__device__ __align__(16) __nv_bfloat16 g_kh[NB*H*L_SEQ*HD], g_kl[NB*H*L_SEQ*HD];   // (n,h,l,d)
__device__ __align__(16) __nv_bfloat16 g_vTh[NB*H*HD*L_SEQ], g_vTl[NB*H*HD*L_SEQ]; // (n,h,d,l)
__device__ __align__(16) __nv_bfloat16 g_ph[NB*H*L_SEQ*L_SEQ], g_pl[NB*H*L_SEQ*L_SEQ]; // probs

// =================== PTX helpers (sm_80-compatible only) ===================
__device__ __forceinline__ uint32_t smem_u32(const void* p) {
    uint32_t a;
    asm("{ .reg .u64 t; cvta.to.shared.u64 t, %1; cvt.u32.u64 %0, t; }" : "=r"(a) : "l"(p));
    return a;
}
__device__ __forceinline__ void cp16(uint32_t dst, const void* src) {
    asm volatile("cp.async.cg.shared.global [%0], [%1], 16;\n" :: "r"(dst), "l"(src));
}
__device__ __forceinline__ void ldm4(uint32_t* r, uint32_t a) {
    asm volatile("ldmatrix.sync.aligned.m8n8.x4.shared.b16 {%0,%1,%2,%3}, [%4];"
                 : "=r"(r[0]), "=r"(r[1]), "=r"(r[2]), "=r"(r[3]) : "r"(a));
}
__device__ __forceinline__ void mma16816(float* d, const uint32_t* a, uint32_t b0, uint32_t b1) {
    asm volatile(
        "mma.sync.aligned.m16n8k16.row.col.f32.bf16.bf16.f32 "
        "{%0,%1,%2,%3}, {%4,%5,%6,%7}, {%8,%9}, {%0,%1,%2,%3};"
        : "+f"(d[0]), "+f"(d[1]), "+f"(d[2]), "+f"(d[3])
        : "r"(a[0]), "r"(a[1]), "r"(a[2]), "r"(a[3]), "r"(b0), "r"(b1));
}
__device__ __forceinline__ void split4(float4 x, uint2& h, uint2& l) {
    __nv_bfloat16 h0 = __float2bfloat16(x.x), h1 = __float2bfloat16(x.y);
    __nv_bfloat16 h2 = __float2bfloat16(x.z), h3 = __float2bfloat16(x.w);
    __nv_bfloat162 hh0(h0, h1), hh1(h2, h3);
    h.x = *(uint32_t*)&hh0; h.y = *(uint32_t*)&hh1;
    __nv_bfloat162 ll0(__float2bfloat16(x.x - __bfloat162float(h0)),
                       __float2bfloat16(x.y - __bfloat162float(h1)));
    __nv_bfloat162 ll1(__float2bfloat16(x.z - __bfloat162float(h2)),
                       __float2bfloat16(x.w - __bfloat162float(h3)));
    l.x = *(uint32_t*)&ll0; l.y = *(uint32_t*)&ll1;
}
__device__ __forceinline__ void split1(float v, __nv_bfloat16& h, __nv_bfloat16& l) {
    h = __float2bfloat16(v);
    l = __float2bfloat16(v - __bfloat162float(h));
}

// =================== tensor-core GEMM (mma.sync, fused fp32->hi/lo) =======
#define SA 40
#define TILE_BYTES (128 * SA * 2)
#define STAGE_BYTES (4 * TILE_BYTES)
#define OFF_AH 0
#define OFF_AL (1 * TILE_BYTES)
#define OFF_BH (2 * TILE_BYTES)
#define OFF_BL (3 * TILE_BYTES)
#define SM_TOTAL (2 * STAGE_BYTES)      // 81920

__global__ void __launch_bounds__(256, 1) tgemm(
    const float* __restrict__ A,
    const float* __restrict__ B0, const float* __restrict__ B1, const float* __restrict__ B2,
    const float* __restrict__ b0, const float* __restrict__ b1, const float* __restrict__ b2,
    float* __restrict__ C, int M, int N, int K, int klen, int mode)
{
    extern __shared__ char smem[];
    const uint32_t sb = smem_u32(smem);
    const int tid = threadIdx.x;
    const int lane = tid & 31, wid = tid >> 5;
    const int wm = wid & 3, wn = wid >> 2;
    const int row0 = blockIdx.y * 128, col0 = blockIdx.x * 128;
    const int kz = blockIdx.z;
    const int koff = kz * klen;

    const float* B = B0;
    int colb = col0;
    if (mode == 2) {
        int seg = col0 / E;
        B = (seg == 0) ? B0 : ((seg == 1) ? B1 : B2);
        colb = col0 - seg * E;
    }

    float acc[2][8][4];
#pragma unroll
    for (int i = 0; i < 2; i++)
#pragma unroll
        for (int j = 0; j < 8; j++)
#pragma unroll
            for (int r = 0; r < 4; r++) acc[i][j][r] = 0.f;

    const int niter = klen >> 5;
    float4 ra[4], rb[4];

    auto ldreg = [&](int it) {
#pragma unroll
        for (int u = 0; u < 4; u++) {
            int e = tid + u * 256;
            int rr = e >> 3, cc = e & 7;
            ra[u] = *(const float4*)(A + (long)(row0 + rr) * K + koff + it * 32 + cc * 4);
            rb[u] = *(const float4*)(B + (long)(colb + rr) * K + koff + it * 32 + cc * 4);
        }
    };
    auto store_stage = [&](int s) {
        char* p = smem + s * STAGE_BYTES;
#pragma unroll
        for (int u = 0; u < 4; u++) {
            int e = tid + u * 256;
            int rr = e >> 3, cc = e & 7;
            uint32_t off = (uint32_t)((rr * SA + cc * 4) * 2);
            uint2 h, l;
            split4(ra[u], h, l);
            *(uint2*)(p + OFF_AH + off) = h;
            *(uint2*)(p + OFF_AL + off) = l;
            split4(rb[u], h, l);
            *(uint2*)(p + OFF_BH + off) = h;
            *(uint2*)(p + OFF_BL + off) = l;
        }
    };
    auto compute = [&](int s) {
        const uint32_t base = sb + s * STAGE_BYTES;
#pragma unroll
        for (int ks = 0; ks < 2; ks++) {
            const uint32_t kcol = (uint32_t)((ks * 16 + (lane >> 4) * 8) * 2);
            uint32_t ah[2][4], al[2][4];
            const uint32_t arow = (uint32_t)(wm * 32 + (lane & 15));
#pragma unroll
            for (int t = 0; t < 2; t++) {
                uint32_t off = ((arow + t * 16) * SA) * 2 + kcol;
                ldm4(ah[t], base + OFF_AH + off);
                ldm4(al[t], base + OFF_AL + off);
            }
            uint32_t bh[4][4], bl[4][4];
            const uint32_t brow = (uint32_t)(wn * 64 + (lane & 15));
#pragma unroll
            for (int u = 0; u < 4; u++) {
                uint32_t off = ((brow + u * 16) * SA) * 2 + kcol;
                ldm4(bh[u], base + OFF_BH + off);
                ldm4(bl[u], base + OFF_BL + off);
            }
#pragma unroll
            for (int mt = 0; mt < 2; mt++)
#pragma unroll
                for (int nt = 0; nt < 8; nt++) {
                    int u = nt >> 1, p = nt & 1;
                    mma16816(acc[mt][nt], ah[mt], bh[u][p], bh[u][p + 2]);
                    mma16816(acc[mt][nt], ah[mt], bl[u][p], bl[u][p + 2]);
                    mma16816(acc[mt][nt], al[mt], bh[u][p], bh[u][p + 2]);
                }
        }
    };

    ldreg(0);
    for (int it = 0; it < niter; it++) {
        const int s = it & 1;
        __syncthreads();
        store_stage(s);
        if (it + 1 < niter) ldreg(it + 1);
        __syncthreads();
        compute(s);
    }

    const int rl = lane >> 2, cl = (lane & 3) * 2;
#pragma unroll
    for (int mt = 0; mt < 2; mt++) {
#pragma unroll
        for (int g = 0; g < 2; g++) {
            const int m = row0 + wm * 32 + mt * 16 + g * 8 + rl;
#pragma unroll
            for (int nt = 0; nt < 8; nt++) {
                const int n = col0 + wn * 64 + nt * 8 + cl;
                float v0 = acc[mt][nt][2 * g];
                float v1 = acc[mt][nt][2 * g + 1];
                if (mode == 0) {
                    if (b0 && kz == 0) { v0 += b0[n]; v1 += b0[n + 1]; }
                    *(float2*)(C + (long)kz * M * N + (long)m * N + n) = make_float2(v0, v1);
                } else if (mode == 1) {
                    v0 += b0[n]; v1 += b0[n + 1];
                    v0 = 0.5f * v0 * (1.0f + erff(v0 * 0.70710678118654752f));
                    v1 = 0.5f * v1 * (1.0f + erff(v1 * 0.70710678118654752f));
                    *(float2*)(C + (long)m * N + n) = make_float2(v0, v1);
                } else { // mode 2: QKV scatter -> bf16 hi/lo operand layouts
                    const int l = m >> 2, nbb = m & 3;
#pragma unroll
                    for (int q = 0; q < 2; q++) {
                        int gcol = n + q;
                        float v = q ? v1 : v0;
                        int seg = gcol / E;
                        int cc = gcol - seg * E;
                        int hh = cc >> 6, dd = cc & 63;
                        __nv_bfloat16 hb, lb;
                        if (seg == 0) {
                            split1((v + b0[cc]) * 0.125f, hb, lb);
                            long idx = (((long)(nbb * H + hh)) * L_SEQ + l) * HD + dd;
                            g_qh[idx] = hb; g_ql[idx] = lb;
                        } else if (seg == 1) {
                            split1(v + b1[cc], hb, lb);
                            long idx = (((long)(nbb * H + hh)) * L_SEQ + l) * HD + dd;
                            g_kh[idx] = hb; g_kl[idx] = lb;
                        } else {
                            split1(v + b2[cc], hb, lb);
                            long idx = (((long)(nbb * H + hh)) * HD + dd) * L_SEQ + l;
                            g_vTh[idx] = hb; g_vTl[idx] = lb;
                        }
                    }
                }
            }
        }
    }
}

// ======= pre-split bf16 hi/lo batched GEMM (attention) =======
// A[*,K], B[*,K] bf16 hi/lo, batched over blockIdx.z with element strides.
// MODE 0: scores -> C[bz*L*L + m*L + n]
// MODE 1: ctx    -> C[((m*NB+nb)*E + hh*HD + n)], bz = nb*H+hh
template<int TM, int TN, int NWM, int MODE>
__global__ void __launch_bounds__(256, 1) pgemm(
    const __nv_bfloat16* __restrict__ Ah, const __nv_bfloat16* __restrict__ Al,
    const __nv_bfloat16* __restrict__ Bh, const __nv_bfloat16* __restrict__ Bl,
    float* __restrict__ C, int K, long sA, long sB)
{
    constexpr int TILE_A = TM * SA * 2;
    constexpr int TILE_B = TN * SA * 2;
    constexpr int STG = 2 * TILE_A + 2 * TILE_B;
    constexpr int O_AH = 0, O_AL = TILE_A, O_BH = 2 * TILE_A, O_BL = 2 * TILE_A + TILE_B;

    extern __shared__ char smem[];
    const uint32_t sb = smem_u32(smem);
    const int tid = threadIdx.x;
    const int lane = tid & 31, wid = tid >> 5;
    const int wm = wid % NWM, wn = wid / NWM;
    const int row0 = blockIdx.y * TM, col0 = blockIdx.x * TN;
    const int bz = blockIdx.z;

    const __nv_bfloat16* pAh = Ah + (long)bz * sA;
    const __nv_bfloat16* pAl = Al + (long)bz * sA;
    const __nv_bfloat16* pBh = Bh + (long)bz * sB;
    const __nv_bfloat16* pBl = Bl + (long)bz * sB;

    float acc[2][8][4];
#pragma unroll
    for (int i = 0; i < 2; i++)
#pragma unroll
        for (int j = 0; j < 8; j++)
#pragma unroll
            for (int r = 0; r < 4; r++) acc[i][j][r] = 0.f;

    const int niter = K >> 5;

    auto load = [&](int it, int s) {
        const int koff = it * 32;
        char* p = smem + s * STG;
        for (int e = tid; e < TM * 4; e += 256) {
            int rr = e >> 2, cc = e & 3;
            uint32_t off = (uint32_t)((rr * SA + cc * 8) * 2);
            long go = (long)(row0 + rr) * K + koff + cc * 8;
            cp16(sb + (uint32_t)(s * STG) + O_AH + off, pAh + go);
            cp16(sb + (uint32_t)(s * STG) + O_AL + off, pAl + go);
        }
        for (int e = tid; e < TN * 4; e += 256) {
            int rr = e >> 2, cc = e & 3;
            uint32_t off = (uint32_t)((rr * SA + cc * 8) * 2);
            long go = (long)(col0 + rr) * K + koff + cc * 8;
            cp16(sb + (uint32_t)(s * STG) + O_BH + off, pBh + go);
            cp16(sb + (uint32_t)(s * STG) + O_BL + off, pBl + go);
        }
        (void)p;
        asm volatile("cp.async.commit_group;" ::: "memory");
    };
    auto compute = [&](int s) {
        const uint32_t base = sb + (uint32_t)(s * STG);
#pragma unroll
        for (int ks = 0; ks < 2; ks++) {
            const uint32_t kcol = (uint32_t)((ks * 16 + (lane >> 4) * 8) * 2);
            uint32_t ah[2][4], al[2][4];
            const uint32_t arow = (uint32_t)(wm * 32 + (lane & 15));
#pragma unroll
            for (int t = 0; t < 2; t++) {
                uint32_t off = ((arow + t * 16) * SA) * 2 + kcol;
                ldm4(ah[t], base + O_AH + off);
                ldm4(al[t], base + O_AL + off);
            }
            uint32_t bh[4][4], bl[4][4];
            const uint32_t brow = (uint32_t)(wn * 64 + (lane & 15));
#pragma unroll
            for (int u = 0; u < 4; u++) {
                uint32_t off = ((brow + u * 16) * SA) * 2 + kcol;
                ldm4(bh[u], base + O_BH + off);
                ldm4(bl[u], base + O_BL + off);
            }
#pragma unroll
            for (int mt = 0; mt < 2; mt++)
#pragma unroll
                for (int nt = 0; nt < 8; nt++) {
                    int u = nt >> 1, p = nt & 1;
                    mma16816(acc[mt][nt], ah[mt], bh[u][p], bh[u][p + 2]);
                    mma16816(acc[mt][nt], ah[mt], bl[u][p], bl[u][p + 2]);
                    mma16816(acc[mt][nt], al[mt], bh[u][p], bh[u][p + 2]);
                }
        }
    };

    load(0, 0);
    for (int it = 0; it < niter; it++) {
        if (it + 1 < niter) {
            load(it + 1, (it + 1) & 1);
            asm volatile("cp.async.wait_group 1;" ::: "memory");
        } else {
            asm volatile("cp.async.wait_group 0;" ::: "memory");
        }
        __syncthreads();
        compute(it & 1);
        __syncthreads();
    }

    const int rl = lane >> 2, cl = (lane & 3) * 2;
#pragma unroll
    for (int mt = 0; mt < 2; mt++) {
#pragma unroll
        for (int g = 0; g < 2; g++) {
            const int m = row0 + wm * 32 + mt * 16 + g * 8 + rl;
#pragma unroll
            for (int nt = 0; nt < 8; nt++) {
                const int n = col0 + wn * 64 + nt * 8 + cl;
                float v0 = acc[mt][nt][2 * g];
                float v1 = acc[mt][nt][2 * g + 1];
                if (MODE == 0) {
                    *(float2*)(C + (long)bz * L_SEQ * L_SEQ + (long)m * L_SEQ + n) =
                        make_float2(v0, v1);
                } else {
                    const int nb = bz / H, hh = bz % H;
                    *(float2*)(C + ((long)m * NB + nb) * E + hh * HD + n) =
                        make_float2(v0, v1);
                }
            }
        }
    }
}

// ---- qp[n,h,i,c] = sum_d q[n,h,i,d]*p_w[h*64+d,c]; qb = q . p_b ---------
__global__ void qp2_kernel(const float* __restrict__ p_w, const float* __restrict__ p_b)
{
    const int h = blockIdx.y;
    const int m0 = blockIdx.x * 64;
    __shared__ float w[64][65];
    __shared__ float qs[64][65];
    __shared__ float pb[64];
    const int tid = threadIdx.x;          // 256
    for (int e = tid; e < 4096; e += 256) {
        int d = e >> 6, c = e & 63;
        w[d][c] = p_w[(h * 64 + d) * 64 + c];
    }
    if (tid < 64) pb[tid] = p_b[h * 64 + tid];
    for (int e = tid; e < 4096; e += 256) {
        int r = e >> 6, d = e & 63;
        int mg = m0 + r;
        int n = mg >> 8, l = mg & 255;
        long idx = (((long)(n * H + h)) * L_SEQ + l) * HD + d;
        qs[r][d] = __bfloat162float(g_qh[idx]) + __bfloat162float(g_ql[idx]);
    }
    __syncthreads();

    const int rr = tid >> 2, cg = tid & 3;
    float acc[16];
#pragma unroll
    for (int c = 0; c < 16; c++) acc[c] = 0.f;
#pragma unroll
    for (int d = 0; d < 64; d++) {
        float qv = qs[rr][d];
#pragma unroll
        for (int c = 0; c < 16; c++) acc[c] += qv * w[d][cg * 16 + c];
    }
    const int mg = m0 + rr;
    const int n = mg >> 8, l = mg & 255;
    const long base = (((long)(n * H + h)) * L_SEQ + l) * HD;
#pragma unroll
    for (int c = 0; c < 16; c++) g_qp[base + cg * 16 + c] = acc[c];
    if (cg == 0) {
        float sb = 0.f;
#pragma unroll
        for (int d = 0; d < 64; d++) sb += qs[rr][d] * pb[d];
        g_qb[((long)n * H + h) * L_SEQ + l] = sb;
    }
}

// ---- scores[n,h,i,j] += sum_c qp[n,h,i,c]*pos[n,i,j,c] + qb[n,h,i] ------
__global__ void cp_kernel(const float* __restrict__ pos)
{
    const int b = blockIdx.x;            // n*L + i
    const int n = b / L_SEQ, i = b % L_SEQ;
    const int j = threadIdx.x;           // 256 threads
    __shared__ __align__(16) float qps[H * 64];
    __shared__ float qbs[H];
    for (int e = j; e < H * 64; e += 256) {
        int hh = e >> 6, c = e & 63;
        qps[e] = g_qp[(((long)n * H + hh) * L_SEQ + i) * HD + c];
    }
    if (j < H) qbs[j] = g_qb[((long)n * H + j) * L_SEQ + i];
    __syncthreads();

    const float4* pr = (const float4*)(pos + ((((long)n * L_SEQ + i) * L_SEQ) + j) * 64);
    float s[H];
#pragma unroll
    for (int hh = 0; hh < H; hh++) s[hh] = 0.f;
#pragma unroll
    for (int cc = 0; cc < 16; cc++) {
        float4 pv = pr[cc];
#pragma unroll
        for (int hh = 0; hh < H; hh++) {
            float4 qv = *(const float4*)&qps[hh * 64 + cc * 4];   // LDS.128 broadcast
            s[hh] += qv.x * pv.x + qv.y * pv.y + qv.z * pv.z + qv.w * pv.w;
        }
    }
#pragma unroll
    for (int hh = 0; hh < H; hh++) {
        long idx = ((((long)n * H + hh) * L_SEQ + i) * L_SEQ) + j;
        g_scores[idx] += s[hh] + qbs[hh];
    }
}

// ---- row softmax over last dim (256); writes probs as bf16 hi/lo --------
__global__ void softmax_kernel()
{
    const long row = blockIdx.x;
    const int j = threadIdx.x;
    __shared__ float red[8];
    float x = g_scores[row * L_SEQ + j];
    float m = x;
#pragma unroll
    for (int o = 16; o > 0; o >>= 1) m = fmaxf(m, __shfl_xor_sync(0xffffffffu, m, o));
    if ((j & 31) == 0) red[j >> 5] = m;
    __syncthreads();
    if (j < 32) {
        float t = (j < 8) ? red[j] : -1e30f;
#pragma unroll
        for (int o = 4; o > 0; o >>= 1) t = fmaxf(t, __shfl_xor_sync(0xffffffffu, t, o));
        if (j == 0) red[0] = t;
    }
    __syncthreads();
    m = red[0];
    float e = __expf(x - m);
    float s = e;
#pragma unroll
    for (int o = 16; o > 0; o >>= 1) s += __shfl_xor_sync(0xffffffffu, s, o);
    __syncthreads();
    if ((j & 31) == 0) red[j >> 5] = s;
    __syncthreads();
    if (j < 32) {
        float t = (j < 8) ? red[j] : 0.f;
#pragma unroll
        for (int o = 4; o > 0; o >>= 1) t += __shfl_xor_sync(0xffffffffu, t, o);
        if (j == 0) red[0] = t;
    }
    __syncthreads();
    float p = e / red[0];
    __nv_bfloat16 hb, lb;
    split1(p, hb, lb);
    g_ph[row * L_SEQ + j] = hb;
    g_pl[row * L_SEQ + j] = lb;
}

// ---- out = LayerNorm(a + sum_{z<np} p[z*ps + .]) * gamma + beta ---------
__global__ void ln_multi(const float* __restrict__ a, const float* __restrict__ p,
                         int nparts, long pstride,
                         const float* __restrict__ gamma, const float* __restrict__ beta,
                         float* __restrict__ out)
{
    const int row = blockIdx.x;
    const int t = threadIdx.x;
    __shared__ float rs[8], rq[8];
    float v[3];
    float s = 0.f, s2 = 0.f;
#pragma unroll
    for (int u = 0; u < 3; u++) {
        long idx = (long)row * E + t + u * 256;
        float x = a[idx];
        for (int z = 0; z < nparts; z++) x += p[z * pstride + idx];
        v[u] = x; s += x; s2 += x * x;
    }
#pragma unroll
    for (int o = 16; o > 0; o >>= 1) {
        s  += __shfl_xor_sync(0xffffffffu, s, o);
        s2 += __shfl_xor_sync(0xffffffffu, s2, o);
    }
    if ((t & 31) == 0) { rs[t >> 5] = s; rq[t >> 5] = s2; }
    __syncthreads();
    if (t < 32) {
        float a1 = (t < 8) ? rs[t] : 0.f;
        float a2 = (t < 8) ? rq[t] : 0.f;
#pragma unroll
        for (int o = 4; o > 0; o >>= 1) {
            a1 += __shfl_xor_sync(0xffffffffu, a1, o);
            a2 += __shfl_xor_sync(0xffffffffu, a2, o);
        }
        if (t == 0) { rs[0] = a1; rq[0] = a2; }
    }
    __syncthreads();
    float mean = rs[0] * (1.f / 768.f);
    float var  = rq[0] * (1.f / 768.f) - mean * mean;
    float r = rsqrtf(var + 1e-5f);
#pragma unroll
    for (int u = 0; u < 3; u++) {
        int c = t + u * 256;
        out[(long)row * E + c] = (v[u] - mean) * r * gamma[c] + beta[c];
    }
}

// =================== host launcher ===================
extern "C" void kernel_launch(void* const* d_in, const int* in_sizes, int n_in,
                              void* d_out, int out_size)
{
    const float* src    = (const float*)d_in[0];
    const float* pos    = (const float*)d_in[1];
    const float* q_w    = (const float*)d_in[2];
    const float* q_b    = (const float*)d_in[3];
    const float* k_w    = (const float*)d_in[4];
    const float* k_b    = (const float*)d_in[5];
    const float* v_w    = (const float*)d_in[6];
    const float* v_b    = (const float*)d_in[7];
    const float* p_w    = (const float*)d_in[8];
    const float* p_b    = (const float*)d_in[9];
    const float* out_w  = (const float*)d_in[10];
    const float* out_b  = (const float*)d_in[11];
    const float* lin1_w = (const float*)d_in[12];
    const float* lin1_b = (const float*)d_in[13];
    const float* lin2_w = (const float*)d_in[14];
    const float* lin2_b = (const float*)d_in[15];
    const float* n1_g   = (const float*)d_in[16];
    const float* n1_b   = (const float*)d_in[17];
    const float* n2_g   = (const float*)d_in[18];
    const float* n2_b   = (const float*)d_in[19];
    float* out = (float*)d_out;

    auto pg_scores = pgemm<128, 128, 4, 0>;
    auto pg_ctx    = pgemm<256, 64, 8, 1>;
    cudaFuncSetAttribute(tgemm, cudaFuncAttributeMaxDynamicSharedMemorySize, SM_TOTAL);
    cudaFuncSetAttribute(pg_scores, cudaFuncAttributeMaxDynamicSharedMemorySize,
                         2 * (4 * 128 * SA * 2));                // 81920
    cudaFuncSetAttribute(pg_ctx, cudaFuncAttributeMaxDynamicSharedMemorySize,
                         2 * (2 * 256 * SA * 2 + 2 * 64 * SA * 2)); // 102400

    float *pscores, *pctx, *pattn, *px1, *pff1, *pff2;
    cudaGetSymbolAddress((void**)&pscores, g_scores);
    cudaGetSymbolAddress((void**)&pctx,    g_ctx);
    cudaGetSymbolAddress((void**)&pattn,   g_attnout);
    cudaGetSymbolAddress((void**)&px1,     g_x1);
    cudaGetSymbolAddress((void**)&pff1,    g_ff1);
    cudaGetSymbolAddress((void**)&pff2,    g_ff2);

    __nv_bfloat16 *qh, *ql, *kh, *kl, *vTh, *vTl, *ph, *pl;
    cudaGetSymbolAddress((void**)&qh,  g_qh);  cudaGetSymbolAddress((void**)&ql,  g_ql);
    cudaGetSymbolAddress((void**)&kh,  g_kh);  cudaGetSymbolAddress((void**)&kl,  g_kl);
    cudaGetSymbolAddress((void**)&vTh, g_vTh); cudaGetSymbolAddress((void**)&vTl, g_vTl);
    cudaGetSymbolAddress((void**)&ph,  g_ph);  cudaGetSymbolAddress((void**)&pl,  g_pl);

    // ---- fused QKV projection, epilogue writes bf16 hi/lo operand layouts ----
    tgemm<<<dim3(3 * E / 128, NTOK / 128, 1), 256, SM_TOTAL>>>(
        src, q_w, k_w, v_w, q_b, k_b, v_b,
        nullptr, NTOK, 3 * E, E, E, 2);

    // ---- attention ----
    qp2_kernel<<<dim3(16, 12), 256>>>(p_w, p_b);
    pg_scores<<<dim3(2, 2, NHB), 256, 81920>>>(
        qh, ql, kh, kl, pscores, HD, (long)L_SEQ * HD, (long)L_SEQ * HD);
    cp_kernel<<<NB * L_SEQ, 256>>>(pos);
    softmax_kernel<<<NB * H * L_SEQ, 256>>>();
    pg_ctx<<<dim3(1, 1, NHB), 256, 102400>>>(
        ph, pl, vTh, vTl, pctx, L_SEQ, (long)L_SEQ * L_SEQ, (long)HD * L_SEQ);

    // ---- output projection (split-K=2) ----
    tgemm<<<dim3(E / 128, NTOK / 128, 2), 256, SM_TOTAL>>>(
        pctx, out_w, nullptr, nullptr, out_b, nullptr, nullptr,
        pattn, NTOK, E, E, E / 2, 0);

    // ---- x1 = LN(src + partials) ----
    ln_multi<<<NTOK, 256>>>(src, pattn, 2, (long)NTOK * E, n1_g, n1_b, px1);

    // ---- FFN ----
    tgemm<<<dim3(FF / 128, NTOK / 128, 1), 256, SM_TOTAL>>>(
        px1, lin1_w, nullptr, nullptr, lin1_b, nullptr, nullptr,
        pff1, NTOK, FF, E, E, 1);
    tgemm<<<dim3(E / 128, NTOK / 128, 4), 256, SM_TOTAL>>>(
        pff1, lin2_w, nullptr, nullptr, lin2_b, nullptr, nullptr,
        pff2, NTOK, E, FF, FF / 4, 0);

    // ---- out = LN(x1 + 4 partials) ----
    ln_multi<<<NTOK, 256>>>(px1, pff2, 4, (long)NTOK * E, n2_g, n2_b, out);
}

// round 8
// speedup vs baseline: 5.3552x; 1.2857x over previous
#include <cuda_runtime.h>
#include <cuda_fp16.h>
#include <math.h>
#include <stdint.h>

#define L_SEQ 256
#define NB    4
#define H     12
#define HD    64
#define E     768
#define FF    3072
#define NTOK  (L_SEQ * NB)   // 1024
#define NHB   (NB * H)       // 48

// ---------------- fp32 scratch ----------------
__device__ float g_qp[NB*H*L_SEQ*HD];
__device__ float g_qb[NB*H*L_SEQ];
__device__ float g_scores[NB*H*L_SEQ*L_SEQ];
__device__ float g_ctx[NTOK*E];
__device__ float g_attnout[2*NTOK*E];      // 2 split-K partials
__device__ float g_x1[NTOK*E];
__device__ float g_ff1[NTOK*FF];
__device__ float g_ff2[4*NTOK*E];          // 4 split-K partials

// ---------------- fp16 operands ----------------
__device__ __align__(16) __half g_qh[NB*H*L_SEQ*HD], g_ql[NB*H*L_SEQ*HD];   // (n,h,l,d)*0.125 hi/lo
__device__ __align__(16) __half g_kh[NB*H*L_SEQ*HD];                        // (n,h,l,d) single
__device__ __align__(16) __half g_vTh[NB*H*HD*L_SEQ];                       // (n,h,d,l) single
__device__ __align__(16) __half g_ph[NB*H*L_SEQ*L_SEQ], g_pl[NB*H*L_SEQ*L_SEQ]; // probs hi/lo

// =================== PTX helpers (sm_80-compatible only) ===================
__device__ __forceinline__ uint32_t smem_u32(const void* p) {
    uint32_t a;
    asm("{ .reg .u64 t; cvta.to.shared.u64 t, %1; cvt.u32.u64 %0, t; }" : "=r"(a) : "l"(p));
    return a;
}
__device__ __forceinline__ void cp16(uint32_t dst, const void* src) {
    asm volatile("cp.async.cg.shared.global [%0], [%1], 16;\n" :: "r"(dst), "l"(src));
}
__device__ __forceinline__ void ldm4(uint32_t* r, uint32_t a) {
    asm volatile("ldmatrix.sync.aligned.m8n8.x4.shared.b16 {%0,%1,%2,%3}, [%4];"
                 : "=r"(r[0]), "=r"(r[1]), "=r"(r[2]), "=r"(r[3]) : "r"(a));
}
__device__ __forceinline__ void mma16816(float* d, const uint32_t* a, uint32_t b0, uint32_t b1) {
    asm volatile(
        "mma.sync.aligned.m16n8k16.row.col.f32.f16.f16.f32 "
        "{%0,%1,%2,%3}, {%4,%5,%6,%7}, {%8,%9}, {%0,%1,%2,%3};"
        : "+f"(d[0]), "+f"(d[1]), "+f"(d[2]), "+f"(d[3])
        : "r"(a[0]), "r"(a[1]), "r"(a[2]), "r"(a[3]), "r"(b0), "r"(b1));
}
// fp32x4 -> fp16 hi (uint2) + lo (uint2)
__device__ __forceinline__ void split4(float4 x, uint2& h, uint2& l) {
    __half h0 = __float2half(x.x), h1 = __float2half(x.y);
    __half h2 = __float2half(x.z), h3 = __float2half(x.w);
    __half2 hh0(h0, h1), hh1(h2, h3);
    h.x = *(uint32_t*)&hh0; h.y = *(uint32_t*)&hh1;
    __half2 ll0(__float2half(x.x - __half2float(h0)),
                __float2half(x.y - __half2float(h1)));
    __half2 ll1(__float2half(x.z - __half2float(h2)),
                __float2half(x.w - __half2float(h3)));
    l.x = *(uint32_t*)&ll0; l.y = *(uint32_t*)&ll1;
}
// fp32x4 -> fp16 single (uint2)
__device__ __forceinline__ void pack4(float4 x, uint2& h) {
    __half2 hh0(__float2half(x.x), __float2half(x.y));
    __half2 hh1(__float2half(x.z), __float2half(x.w));
    h.x = *(uint32_t*)&hh0; h.y = *(uint32_t*)&hh1;
}
__device__ __forceinline__ void split1(float v, __half& h, __half& l) {
    h = __float2half(v);
    l = __float2half(v - __half2float(h));
}

// ============ tensor-core GEMM: A fp32 (split hi/lo in-kernel) × B fp32
// (rounded fp16 in-kernel), 2-term product. 128x128 tile, BK=32, 8 warps. ===
#define SA 40
#define TILE_BYTES (128 * SA * 2)
#define STAGE_BYTES (3 * TILE_BYTES)
#define OFF_AH 0
#define OFF_AL (1 * TILE_BYTES)
#define OFF_BH (2 * TILE_BYTES)
#define SM_TOTAL (2 * STAGE_BYTES)      // 61440

__global__ void __launch_bounds__(256, 1) tgemm(
    const float* __restrict__ A,
    const float* __restrict__ B0, const float* __restrict__ B1, const float* __restrict__ B2,
    const float* __restrict__ b0, const float* __restrict__ b1, const float* __restrict__ b2,
    float* __restrict__ C, int M, int N, int K, int klen, int mode)
{
    extern __shared__ char smem[];
    const uint32_t sb = smem_u32(smem);
    const int tid = threadIdx.x;
    const int lane = tid & 31, wid = tid >> 5;
    const int wm = wid & 3, wn = wid >> 2;
    const int row0 = blockIdx.y * 128, col0 = blockIdx.x * 128;
    const int kz = blockIdx.z;
    const int koff = kz * klen;

    const float* B = B0;
    int colb = col0;
    if (mode == 2) {
        int seg = col0 / E;
        B = (seg == 0) ? B0 : ((seg == 1) ? B1 : B2);
        colb = col0 - seg * E;
    }

    float acc[2][8][4];
#pragma unroll
    for (int i = 0; i < 2; i++)
#pragma unroll
        for (int j = 0; j < 8; j++)
#pragma unroll
            for (int r = 0; r < 4; r++) acc[i][j][r] = 0.f;

    const int niter = klen >> 5;
    float4 ra[4], rb[4];

    auto ldreg = [&](int it) {
#pragma unroll
        for (int u = 0; u < 4; u++) {
            int e = tid + u * 256;
            int rr = e >> 3, cc = e & 7;
            ra[u] = *(const float4*)(A + (long)(row0 + rr) * K + koff + it * 32 + cc * 4);
            rb[u] = *(const float4*)(B + (long)(colb + rr) * K + koff + it * 32 + cc * 4);
        }
    };
    auto store_stage = [&](int s) {
        char* p = smem + s * STAGE_BYTES;
#pragma unroll
        for (int u = 0; u < 4; u++) {
            int e = tid + u * 256;
            int rr = e >> 3, cc = e & 7;
            uint32_t off = (uint32_t)((rr * SA + cc * 4) * 2);
            uint2 h, l;
            split4(ra[u], h, l);
            *(uint2*)(p + OFF_AH + off) = h;
            *(uint2*)(p + OFF_AL + off) = l;
            pack4(rb[u], h);
            *(uint2*)(p + OFF_BH + off) = h;
        }
    };
    auto compute = [&](int s) {
        const uint32_t base = sb + s * STAGE_BYTES;
#pragma unroll
        for (int ks = 0; ks < 2; ks++) {
            const uint32_t kcol = (uint32_t)((ks * 16 + (lane >> 4) * 8) * 2);
            uint32_t ah[2][4], al[2][4];
            const uint32_t arow = (uint32_t)(wm * 32 + (lane & 15));
#pragma unroll
            for (int t = 0; t < 2; t++) {
                uint32_t off = ((arow + t * 16) * SA) * 2 + kcol;
                ldm4(ah[t], base + OFF_AH + off);
                ldm4(al[t], base + OFF_AL + off);
            }
            uint32_t bh[4][4];
            const uint32_t brow = (uint32_t)(wn * 64 + (lane & 15));
#pragma unroll
            for (int u = 0; u < 4; u++) {
                uint32_t off = ((brow + u * 16) * SA) * 2 + kcol;
                ldm4(bh[u], base + OFF_BH + off);
            }
#pragma unroll
            for (int mt = 0; mt < 2; mt++)
#pragma unroll
                for (int nt = 0; nt < 8; nt++) {
                    int u = nt >> 1, p = nt & 1;
                    mma16816(acc[mt][nt], ah[mt], bh[u][p], bh[u][p + 2]);
                    mma16816(acc[mt][nt], al[mt], bh[u][p], bh[u][p + 2]);
                }
        }
    };

    ldreg(0);
    for (int it = 0; it < niter; it++) {
        const int s = it & 1;
        __syncthreads();
        store_stage(s);
        if (it + 1 < niter) ldreg(it + 1);
        __syncthreads();
        compute(s);
    }

    const int rl = lane >> 2, cl = (lane & 3) * 2;
#pragma unroll
    for (int mt = 0; mt < 2; mt++) {
#pragma unroll
        for (int g = 0; g < 2; g++) {
            const int m = row0 + wm * 32 + mt * 16 + g * 8 + rl;
#pragma unroll
            for (int nt = 0; nt < 8; nt++) {
                const int n = col0 + wn * 64 + nt * 8 + cl;
                float v0 = acc[mt][nt][2 * g];
                float v1 = acc[mt][nt][2 * g + 1];
                if (mode == 0) {
                    if (b0 && kz == 0) { v0 += b0[n]; v1 += b0[n + 1]; }
                    *(float2*)(C + (long)kz * M * N + (long)m * N + n) = make_float2(v0, v1);
                } else if (mode == 1) {
                    v0 += b0[n]; v1 += b0[n + 1];
                    v0 = 0.5f * v0 * (1.0f + erff(v0 * 0.70710678118654752f));
                    v1 = 0.5f * v1 * (1.0f + erff(v1 * 0.70710678118654752f));
                    *(float2*)(C + (long)m * N + n) = make_float2(v0, v1);
                } else { // mode 2: QKV scatter -> fp16 operand layouts
                    const int l = m >> 2, nbb = m & 3;
#pragma unroll
                    for (int q = 0; q < 2; q++) {
                        int gcol = n + q;
                        float v = q ? v1 : v0;
                        int seg = gcol / E;
                        int cc = gcol - seg * E;
                        int hh = cc >> 6, dd = cc & 63;
                        if (seg == 0) {
                            __half hb, lb;
                            split1((v + b0[cc]) * 0.125f, hb, lb);
                            long idx = (((long)(nbb * H + hh)) * L_SEQ + l) * HD + dd;
                            g_qh[idx] = hb; g_ql[idx] = lb;
                        } else if (seg == 1) {
                            long idx = (((long)(nbb * H + hh)) * L_SEQ + l) * HD + dd;
                            g_kh[idx] = __float2half(v + b1[cc]);
                        } else {
                            long idx = (((long)(nbb * H + hh)) * HD + dd) * L_SEQ + l;
                            g_vTh[idx] = __float2half(v + b2[cc]);
                        }
                    }
                }
            }
        }
    }
}

// ======= pre-split fp16 batched GEMM (attention): A hi/lo × B single ======
// MODE 0: scores -> C[bz*L*L + m*L + n]
// MODE 1: ctx    -> C[((m*NB+nb)*E + hh*HD + n)], bz = nb*H+hh
template<int TM, int TN, int NWM, int MODE>
__global__ void __launch_bounds__(256, 1) pgemm(
    const __half* __restrict__ Ah, const __half* __restrict__ Al,
    const __half* __restrict__ Bh,
    float* __restrict__ C, int K, long sA, long sB)
{
    constexpr int TILE_A = TM * SA * 2;
    constexpr int TILE_B = TN * SA * 2;
    constexpr int STG = 2 * TILE_A + TILE_B;
    constexpr int O_AH = 0, O_AL = TILE_A, O_BH = 2 * TILE_A;

    extern __shared__ char smem[];
    const uint32_t sb = smem_u32(smem);
    const int tid = threadIdx.x;
    const int lane = tid & 31, wid = tid >> 5;
    const int wm = wid % NWM, wn = wid / NWM;
    const int row0 = blockIdx.y * TM, col0 = blockIdx.x * TN;
    const int bz = blockIdx.z;

    const __half* pAh = Ah + (long)bz * sA;
    const __half* pAl = Al + (long)bz * sA;
    const __half* pBh = Bh + (long)bz * sB;

    float acc[2][8][4];
#pragma unroll
    for (int i = 0; i < 2; i++)
#pragma unroll
        for (int j = 0; j < 8; j++)
#pragma unroll
            for (int r = 0; r < 4; r++) acc[i][j][r] = 0.f;

    const int niter = K >> 5;

    auto load = [&](int it, int s) {
        const int koff = it * 32;
        for (int e = tid; e < TM * 4; e += 256) {
            int rr = e >> 2, cc = e & 3;
            uint32_t off = (uint32_t)((rr * SA + cc * 8) * 2);
            long go = (long)(row0 + rr) * K + koff + cc * 8;
            cp16(sb + (uint32_t)(s * STG) + O_AH + off, pAh + go);
            cp16(sb + (uint32_t)(s * STG) + O_AL + off, pAl + go);
        }
        for (int e = tid; e < TN * 4; e += 256) {
            int rr = e >> 2, cc = e & 3;
            uint32_t off = (uint32_t)((rr * SA + cc * 8) * 2);
            long go = (long)(col0 + rr) * K + koff + cc * 8;
            cp16(sb + (uint32_t)(s * STG) + O_BH + off, pBh + go);
        }
        asm volatile("cp.async.commit_group;" ::: "memory");
    };
    auto compute = [&](int s) {
        const uint32_t base = sb + (uint32_t)(s * STG);
#pragma unroll
        for (int ks = 0; ks < 2; ks++) {
            const uint32_t kcol = (uint32_t)((ks * 16 + (lane >> 4) * 8) * 2);
            uint32_t ah[2][4], al[2][4];
            const uint32_t arow = (uint32_t)(wm * 32 + (lane & 15));
#pragma unroll
            for (int t = 0; t < 2; t++) {
                uint32_t off = ((arow + t * 16) * SA) * 2 + kcol;
                ldm4(ah[t], base + O_AH + off);
                ldm4(al[t], base + O_AL + off);
            }
            uint32_t bh[4][4];
            const uint32_t brow = (uint32_t)(wn * 64 + (lane & 15));
#pragma unroll
            for (int u = 0; u < 4; u++) {
                uint32_t off = ((brow + u * 16) * SA) * 2 + kcol;
                ldm4(bh[u], base + O_BH + off);
            }
#pragma unroll
            for (int mt = 0; mt < 2; mt++)
#pragma unroll
                for (int nt = 0; nt < 8; nt++) {
                    int u = nt >> 1, p = nt & 1;
                    mma16816(acc[mt][nt], ah[mt], bh[u][p], bh[u][p + 2]);
                    mma16816(acc[mt][nt], al[mt], bh[u][p], bh[u][p + 2]);
                }
        }
    };

    load(0, 0);
    for (int it = 0; it < niter; it++) {
        if (it + 1 < niter) {
            load(it + 1, (it + 1) & 1);
            asm volatile("cp.async.wait_group 1;" ::: "memory");
        } else {
            asm volatile("cp.async.wait_group 0;" ::: "memory");
        }
        __syncthreads();
        compute(it & 1);
        __syncthreads();
    }

    const int rl = lane >> 2, cl = (lane & 3) * 2;
#pragma unroll
    for (int mt = 0; mt < 2; mt++) {
#pragma unroll
        for (int g = 0; g < 2; g++) {
            const int m = row0 + wm * 32 + mt * 16 + g * 8 + rl;
#pragma unroll
            for (int nt = 0; nt < 8; nt++) {
                const int n = col0 + wn * 64 + nt * 8 + cl;
                float v0 = acc[mt][nt][2 * g];
                float v1 = acc[mt][nt][2 * g + 1];
                if (MODE == 0) {
                    *(float2*)(C + (long)bz * L_SEQ * L_SEQ + (long)m * L_SEQ + n) =
                        make_float2(v0, v1);
                } else {
                    const int nb = bz / H, hh = bz % H;
                    *(float2*)(C + ((long)m * NB + nb) * E + hh * HD + n) =
                        make_float2(v0, v1);
                }
            }
        }
    }
}

// ---- qp[n,h,i,c] = sum_d q[n,h,i,d]*p_w[h*64+d,c]; qb = q . p_b ---------
__global__ void qp2_kernel(const float* __restrict__ p_w, const float* __restrict__ p_b)
{
    const int h = blockIdx.y;
    const int m0 = blockIdx.x * 64;
    __shared__ float w[64][65];
    __shared__ float qs[64][65];
    __shared__ float pb[64];
    const int tid = threadIdx.x;          // 256
    for (int e = tid; e < 4096; e += 256) {
        int d = e >> 6, c = e & 63;
        w[d][c] = p_w[(h * 64 + d) * 64 + c];
    }
    if (tid < 64) pb[tid] = p_b[h * 64 + tid];
    for (int e = tid; e < 4096; e += 256) {
        int r = e >> 6, d = e & 63;
        int mg = m0 + r;
        int n = mg >> 8, l = mg & 255;
        long idx = (((long)(n * H + h)) * L_SEQ + l) * HD + d;
        qs[r][d] = __half2float(g_qh[idx]) + __half2float(g_ql[idx]);
    }
    __syncthreads();

    const int rr = tid >> 2, cg = tid & 3;
    float acc[16];
#pragma unroll
    for (int c = 0; c < 16; c++) acc[c] = 0.f;
#pragma unroll
    for (int d = 0; d < 64; d++) {
        float qv = qs[rr][d];
#pragma unroll
        for (int c = 0; c < 16; c++) acc[c] += qv * w[d][cg * 16 + c];
    }
    const int mg = m0 + rr;
    const int n = mg >> 8, l = mg & 255;
    const long base = (((long)(n * H + h)) * L_SEQ + l) * HD;
#pragma unroll
    for (int c = 0; c < 16; c++) g_qp[base + cg * 16 + c] = acc[c];
    if (cg == 0) {
        float sb = 0.f;
#pragma unroll
        for (int d = 0; d < 64; d++) sb += qs[rr][d] * pb[d];
        g_qb[((long)n * H + h) * L_SEQ + l] = sb;
    }
}

// ---- cpm: scores[n,h,i,:] += qp[n,h,i,:] @ pos[n,i,:,:]^T + qb, via MMA --
// One block per (n, i). A = qp (12x64 padded to 16, fp16 hi/lo),
// B = pos tile (256x64, coalesced fp32 load -> fp16 single in smem).
#define CSA 72   // fp16 elements per row (64 + 8 pad)
__global__ void __launch_bounds__(256, 1) cpm_kernel(const float* __restrict__ pos)
{
    __shared__ __align__(16) __half sAh[16 * CSA];
    __shared__ __align__(16) __half sAl[16 * CSA];
    __shared__ __align__(16) __half sB[L_SEQ * CSA];
    __shared__ float qbs[12];

    const int b = blockIdx.x;            // n*L + i
    const int n = b >> 8, i = b & 255;
    const int tid = threadIdx.x;
    const int lane = tid & 31, wid = tid >> 5;

    // A: qp rows (12 heads x 64), rows 12-15 zero
    for (int e = tid; e < 1024; e += 256) {
        int h = e >> 6, c = e & 63;
        float v = (h < 12) ? g_qp[(((long)(n * H + h)) * L_SEQ + i) * HD + c] : 0.f;
        __half hb, lb;
        split1(v, hb, lb);
        sAh[h * CSA + c] = hb;
        sAl[h * CSA + c] = lb;
    }
    if (tid < 12) qbs[tid] = g_qb[((long)n * H + tid) * L_SEQ + i];

    // B: pos[n,i,:,:] 256x64 fp32, coalesced float4 loads
    const float4* pr = (const float4*)(pos + (((long)n * L_SEQ + i) * L_SEQ) * 64);
#pragma unroll
    for (int u = 0; u < 16; u++) {
        int e = tid + u * 256;           // 0..4095
        int rr = e >> 4, cc = e & 15;
        float4 v = pr[e];
        uint2 h;
        pack4(v, h);
        *(uint2*)&sB[rr * CSA + cc * 4] = h;
    }
    __syncthreads();

    const uint32_t aB = smem_u32(sAh), aL = smem_u32(sAl), bB = smem_u32(sB);
    const int n0 = wid * 32;             // warp's j-range

    float acc[4][4];
#pragma unroll
    for (int j = 0; j < 4; j++)
#pragma unroll
        for (int r = 0; r < 4; r++) acc[j][r] = 0.f;

#pragma unroll
    for (int ks = 0; ks < 4; ks++) {
        const uint32_t kcol = (uint32_t)((ks * 16 + (lane >> 4) * 8) * 2);
        uint32_t ah[4], al[4];
        {
            uint32_t off = ((uint32_t)(lane & 15) * CSA) * 2 + kcol;
            ldm4(ah, aB + off);
            ldm4(al, aL + off);
        }
        uint32_t bh[2][4];
#pragma unroll
        for (int t = 0; t < 2; t++) {
            uint32_t off = ((uint32_t)(n0 + (lane & 15) + t * 16) * CSA) * 2 + kcol;
            ldm4(bh[t], bB + off);
        }
#pragma unroll
        for (int nt = 0; nt < 4; nt++) {
            int u = nt >> 1, p = nt & 1;
            mma16816(acc[nt], ah, bh[u][p], bh[u][p + 2]);
            mma16816(acc[nt], al, bh[u][p], bh[u][p + 2]);
        }
    }

    // epilogue: rows 0..11 -> scores += (RMW)
    const int rl = lane >> 2, cl = (lane & 3) * 2;
#pragma unroll
    for (int g = 0; g < 2; g++) {
        const int m = g * 8 + rl;
        if (m < 12) {
            const float qb = qbs[m];
            float* srow = g_scores + ((((long)n * H + m) * L_SEQ + i) * L_SEQ);
#pragma unroll
            for (int nt = 0; nt < 4; nt++) {
                const int j = n0 + nt * 8 + cl;
                float2 old = *(float2*)(srow + j);
                old.x += acc[nt][2 * g] + qb;
                old.y += acc[nt][2 * g + 1] + qb;
                *(float2*)(srow + j) = old;
            }
        }
    }
}

// ---- row softmax over last dim (256); writes probs as fp16 hi/lo --------
__global__ void softmax_kernel()
{
    const long row = blockIdx.x;
    const int j = threadIdx.x;
    __shared__ float red[8];
    float x = g_scores[row * L_SEQ + j];
    float m = x;
#pragma unroll
    for (int o = 16; o > 0; o >>= 1) m = fmaxf(m, __shfl_xor_sync(0xffffffffu, m, o));
    if ((j & 31) == 0) red[j >> 5] = m;
    __syncthreads();
    if (j < 32) {
        float t = (j < 8) ? red[j] : -1e30f;
#pragma unroll
        for (int o = 4; o > 0; o >>= 1) t = fmaxf(t, __shfl_xor_sync(0xffffffffu, t, o));
        if (j == 0) red[0] = t;
    }
    __syncthreads();
    m = red[0];
    float e = __expf(x - m);
    float s = e;
#pragma unroll
    for (int o = 16; o > 0; o >>= 1) s += __shfl_xor_sync(0xffffffffu, s, o);
    __syncthreads();
    if ((j & 31) == 0) red[j >> 5] = s;
    __syncthreads();
    if (j < 32) {
        float t = (j < 8) ? red[j] : 0.f;
#pragma unroll
        for (int o = 4; o > 0; o >>= 1) t += __shfl_xor_sync(0xffffffffu, t, o);
        if (j == 0) red[0] = t;
    }
    __syncthreads();
    float p = e / red[0];
    __half hb, lb;
    split1(p, hb, lb);
    g_ph[row * L_SEQ + j] = hb;
    g_pl[row * L_SEQ + j] = lb;
}

// ---- out = LayerNorm(a + sum_{z<np} p[z*ps + .]) * gamma + beta ---------
__global__ void ln_multi(const float* __restrict__ a, const float* __restrict__ p,
                         int nparts, long pstride,
                         const float* __restrict__ gamma, const float* __restrict__ beta,
                         float* __restrict__ out)
{
    const int row = blockIdx.x;
    const int t = threadIdx.x;
    __shared__ float rs[8], rq[8];
    float v[3];
    float s = 0.f, s2 = 0.f;
#pragma unroll
    for (int u = 0; u < 3; u++) {
        long idx = (long)row * E + t + u * 256;
        float x = a[idx];
        for (int z = 0; z < nparts; z++) x += p[z * pstride + idx];
        v[u] = x; s += x; s2 += x * x;
    }
#pragma unroll
    for (int o = 16; o > 0; o >>= 1) {
        s  += __shfl_xor_sync(0xffffffffu, s, o);
        s2 += __shfl_xor_sync(0xffffffffu, s2, o);
    }
    if ((t & 31) == 0) { rs[t >> 5] = s; rq[t >> 5] = s2; }
    __syncthreads();
    if (t < 32) {
        float a1 = (t < 8) ? rs[t] : 0.f;
        float a2 = (t < 8) ? rq[t] : 0.f;
#pragma unroll
        for (int o = 4; o > 0; o >>= 1) {
            a1 += __shfl_xor_sync(0xffffffffu, a1, o);
            a2 += __shfl_xor_sync(0xffffffffu, a2, o);
        }
        if (t == 0) { rs[0] = a1; rq[0] = a2; }
    }
    __syncthreads();
    float mean = rs[0] * (1.f / 768.f);
    float var  = rq[0] * (1.f / 768.f) - mean * mean;
    float r = rsqrtf(var + 1e-5f);
#pragma unroll
    for (int u = 0; u < 3; u++) {
        int c = t + u * 256;
        out[(long)row * E + c] = (v[u] - mean) * r * gamma[c] + beta[c];
    }
}

// =================== host launcher ===================
extern "C" void kernel_launch(void* const* d_in, const int* in_sizes, int n_in,
                              void* d_out, int out_size)
{
    const float* src    = (const float*)d_in[0];
    const float* pos    = (const float*)d_in[1];
    const float* q_w    = (const float*)d_in[2];
    const float* q_b    = (const float*)d_in[3];
    const float* k_w    = (const float*)d_in[4];
    const float* k_b    = (const float*)d_in[5];
    const float* v_w    = (const float*)d_in[6];
    const float* v_b    = (const float*)d_in[7];
    const float* p_w    = (const float*)d_in[8];
    const float* p_b    = (const float*)d_in[9];
    const float* out_w  = (const float*)d_in[10];
    const float* out_b  = (const float*)d_in[11];
    const float* lin1_w = (const float*)d_in[12];
    const float* lin1_b = (const float*)d_in[13];
    const float* lin2_w = (const float*)d_in[14];
    const float* lin2_b = (const float*)d_in[15];
    const float* n1_g   = (const float*)d_in[16];
    const float* n1_b   = (const float*)d_in[17];
    const float* n2_g   = (const float*)d_in[18];
    const float* n2_b   = (const float*)d_in[19];
    float* out = (float*)d_out;

    auto pg_scores = pgemm<128, 128, 4, 0>;
    auto pg_ctx    = pgemm<256, 64, 8, 1>;
    const int smem_scores = 2 * (2 * 128 * SA * 2 + 128 * SA * 2);          // 61440
    const int smem_ctx    = 2 * (2 * 256 * SA * 2 + 64 * SA * 2);           // 92160
    cudaFuncSetAttribute(tgemm, cudaFuncAttributeMaxDynamicSharedMemorySize, SM_TOTAL);
    cudaFuncSetAttribute(pg_scores, cudaFuncAttributeMaxDynamicSharedMemorySize, smem_scores);
    cudaFuncSetAttribute(pg_ctx, cudaFuncAttributeMaxDynamicSharedMemorySize, smem_ctx);

    float *pscores, *pctx, *pattn, *px1, *pff1, *pff2;
    cudaGetSymbolAddress((void**)&pscores, g_scores);
    cudaGetSymbolAddress((void**)&pctx,    g_ctx);
    cudaGetSymbolAddress((void**)&pattn,   g_attnout);
    cudaGetSymbolAddress((void**)&px1,     g_x1);
    cudaGetSymbolAddress((void**)&pff1,    g_ff1);
    cudaGetSymbolAddress((void**)&pff2,    g_ff2);

    __half *qh, *ql, *kh, *vTh, *ph, *pl;
    cudaGetSymbolAddress((void**)&qh,  g_qh);  cudaGetSymbolAddress((void**)&ql,  g_ql);
    cudaGetSymbolAddress((void**)&kh,  g_kh);
    cudaGetSymbolAddress((void**)&vTh, g_vTh);
    cudaGetSymbolAddress((void**)&ph,  g_ph);  cudaGetSymbolAddress((void**)&pl,  g_pl);

    // ---- fused QKV projection, epilogue writes fp16 operand layouts ----
    tgemm<<<dim3(3 * E / 128, NTOK / 128, 1), 256, SM_TOTAL>>>(
        src, q_w, k_w, v_w, q_b, k_b, v_b,
        nullptr, NTOK, 3 * E, E, E, 2);

    // ---- attention ----
    qp2_kernel<<<dim3(16, 12), 256>>>(p_w, p_b);
    pg_scores<<<dim3(2, 2, NHB), 256, smem_scores>>>(
        qh, ql, kh, pscores, HD, (long)L_SEQ * HD, (long)L_SEQ * HD);
    cpm_kernel<<<NB * L_SEQ, 256>>>(pos);
    softmax_kernel<<<NB * H * L_SEQ, 256>>>();
    pg_ctx<<<dim3(1, 1, NHB), 256, smem_ctx>>>(
        ph, pl, vTh, pctx, L_SEQ, (long)L_SEQ * L_SEQ, (long)HD * L_SEQ);

    // ---- output projection (split-K=2) ----
    tgemm<<<dim3(E / 128, NTOK / 128, 2), 256, SM_TOTAL>>>(
        pctx, out_w, nullptr, nullptr, out_b, nullptr, nullptr,
        pattn, NTOK, E, E, E / 2, 0);

    // ---- x1 = LN(src + partials) ----
    ln_multi<<<NTOK, 256>>>(src, pattn, 2, (long)NTOK * E, n1_g, n1_b, px1);

    // ---- FFN ----
    tgemm<<<dim3(FF / 128, NTOK / 128, 1), 256, SM_TOTAL>>>(
        px1, lin1_w, nullptr, nullptr, lin1_b, nullptr, nullptr,
        pff1, NTOK, FF, E, E, 1);
    tgemm<<<dim3(E / 128, NTOK / 128, 4), 256, SM_TOTAL>>>(
        pff1, lin2_w, nullptr, nullptr, lin2_b, nullptr, nullptr,
        pff2, NTOK, E, FF, FF / 4, 0);

    // ---- out = LN(x1 + 4 partials) ----
    ln_multi<<<NTOK, 256>>>(px1, pff2, 4, (long)NTOK * E, n2_g, n2_b, out);
}

// round 10
// speedup vs baseline: 6.6174x; 1.2357x over previous
#include <cuda_runtime.h>
#include <cuda_fp16.h>
#include <math.h>
#include <stdint.h>

#define L_SEQ 256
#define NB    4
#define H     12
#define HD    64
#define E     768
#define FF    3072
#define NTOK  (L_SEQ * NB)   // 1024
#define NHB   (NB * H)       // 48

// ---------------- fp32 scratch ----------------
__device__ float g_qp[NB*H*L_SEQ*HD];
__device__ float g_qb[NB*H*L_SEQ];
__device__ float g_scores[NB*H*L_SEQ*L_SEQ];
__device__ float g_ctx[NTOK*E];
__device__ float g_attnout[2*NTOK*E];      // 2 split-K partials
__device__ float g_x1[NTOK*E];
__device__ float g_ff1[NTOK*FF];
__device__ float g_ff2[4*NTOK*E];          // 4 split-K partials

// ---------------- fp16 operands ----------------
__device__ __align__(16) __half g_qh[NB*H*L_SEQ*HD], g_ql[NB*H*L_SEQ*HD];   // (n,h,l,d)*0.125 hi/lo
__device__ __align__(16) __half g_kh[NB*H*L_SEQ*HD];                        // (n,h,l,d) single
__device__ __align__(16) __half g_vTh[NB*H*HD*L_SEQ];                       // (n,h,d,l) single
__device__ __align__(16) __half g_ph[NB*H*L_SEQ*L_SEQ], g_pl[NB*H*L_SEQ*L_SEQ]; // probs hi/lo

// =================== PTX helpers (sm_80-compatible only) ===================
__device__ __forceinline__ uint32_t smem_u32(const void* p) {
    uint32_t a;
    asm("{ .reg .u64 t; cvta.to.shared.u64 t, %1; cvt.u32.u64 %0, t; }" : "=r"(a) : "l"(p));
    return a;
}
__device__ __forceinline__ void cp16(uint32_t dst, const void* src) {
    asm volatile("cp.async.cg.shared.global [%0], [%1], 16;\n" :: "r"(dst), "l"(src));
}
__device__ __forceinline__ void ldm4(uint32_t* r, uint32_t a) {
    asm volatile("ldmatrix.sync.aligned.m8n8.x4.shared.b16 {%0,%1,%2,%3}, [%4];"
                 : "=r"(r[0]), "=r"(r[1]), "=r"(r[2]), "=r"(r[3]) : "r"(a));
}
__device__ __forceinline__ void mma16816(float* d, const uint32_t* a, uint32_t b0, uint32_t b1) {
    asm volatile(
        "mma.sync.aligned.m16n8k16.row.col.f32.f16.f16.f32 "
        "{%0,%1,%2,%3}, {%4,%5,%6,%7}, {%8,%9}, {%0,%1,%2,%3};"
        : "+f"(d[0]), "+f"(d[1]), "+f"(d[2]), "+f"(d[3])
        : "r"(a[0]), "r"(a[1]), "r"(a[2]), "r"(a[3]), "r"(b0), "r"(b1));
}
// fp32x4 -> fp16 hi (uint2) + lo (uint2)
__device__ __forceinline__ void split4(float4 x, uint2& h, uint2& l) {
    __half h0 = __float2half(x.x), h1 = __float2half(x.y);
    __half h2 = __float2half(x.z), h3 = __float2half(x.w);
    __half2 hh0(h0, h1), hh1(h2, h3);
    h.x = *(uint32_t*)&hh0; h.y = *(uint32_t*)&hh1;
    __half2 ll0(__float2half(x.x - __half2float(h0)),
                __float2half(x.y - __half2float(h1)));
    __half2 ll1(__float2half(x.z - __half2float(h2)),
                __float2half(x.w - __half2float(h3)));
    l.x = *(uint32_t*)&ll0; l.y = *(uint32_t*)&ll1;
}
// fp32x4 -> fp16 single (uint2)
__device__ __forceinline__ void pack4(float4 x, uint2& h) {
    __half2 hh0(__float2half(x.x), __float2half(x.y));
    __half2 hh1(__float2half(x.z), __float2half(x.w));
    h.x = *(uint32_t*)&hh0; h.y = *(uint32_t*)&hh1;
}
__device__ __forceinline__ void split1(float v, __half& h, __half& l) {
    h = __float2half(v);
    l = __float2half(v - __half2float(h));
}

// ============ tensor-core GEMM: fp32 in, rounded fp16 single both sides ===
#define SA 40
#define TILE_BYTES (128 * SA * 2)
#define STAGE_BYTES (2 * TILE_BYTES)
#define OFF_AH 0
#define OFF_BH (1 * TILE_BYTES)
#define SM_TOTAL (2 * STAGE_BYTES)      // 40960

__global__ void __launch_bounds__(256, 1) tgemm(
    const float* __restrict__ A,
    const float* __restrict__ B0, const float* __restrict__ B1, const float* __restrict__ B2,
    const float* __restrict__ b0, const float* __restrict__ b1, const float* __restrict__ b2,
    float* __restrict__ C, int M, int N, int K, int klen, int mode)
{
    extern __shared__ char smem[];
    const uint32_t sb = smem_u32(smem);
    const int tid = threadIdx.x;
    const int lane = tid & 31, wid = tid >> 5;
    const int wm = wid & 3, wn = wid >> 2;
    const int row0 = blockIdx.y * 128, col0 = blockIdx.x * 128;
    const int kz = blockIdx.z;
    const int koff = kz * klen;

    const float* B = B0;
    int colb = col0;
    if (mode == 2) {
        int seg = col0 / E;
        B = (seg == 0) ? B0 : ((seg == 1) ? B1 : B2);
        colb = col0 - seg * E;
    }

    float acc[2][8][4];
#pragma unroll
    for (int i = 0; i < 2; i++)
#pragma unroll
        for (int j = 0; j < 8; j++)
#pragma unroll
            for (int r = 0; r < 4; r++) acc[i][j][r] = 0.f;

    const int niter = klen >> 5;
    float4 ra[4], rb[4];

    auto ldreg = [&](int it) {
#pragma unroll
        for (int u = 0; u < 4; u++) {
            int e = tid + u * 256;
            int rr = e >> 3, cc = e & 7;
            ra[u] = *(const float4*)(A + (long)(row0 + rr) * K + koff + it * 32 + cc * 4);
            rb[u] = *(const float4*)(B + (long)(colb + rr) * K + koff + it * 32 + cc * 4);
        }
    };
    auto store_stage = [&](int s) {
        char* p = smem + s * STAGE_BYTES;
#pragma unroll
        for (int u = 0; u < 4; u++) {
            int e = tid + u * 256;
            int rr = e >> 3, cc = e & 7;
            uint32_t off = (uint32_t)((rr * SA + cc * 4) * 2);
            uint2 h;
            pack4(ra[u], h);
            *(uint2*)(p + OFF_AH + off) = h;
            pack4(rb[u], h);
            *(uint2*)(p + OFF_BH + off) = h;
        }
    };
    auto compute = [&](int s) {
        const uint32_t base = sb + s * STAGE_BYTES;
#pragma unroll
        for (int ks = 0; ks < 2; ks++) {
            const uint32_t kcol = (uint32_t)((ks * 16 + (lane >> 4) * 8) * 2);
            uint32_t ah[2][4];
            const uint32_t arow = (uint32_t)(wm * 32 + (lane & 15));
#pragma unroll
            for (int t = 0; t < 2; t++) {
                uint32_t off = ((arow + t * 16) * SA) * 2 + kcol;
                ldm4(ah[t], base + OFF_AH + off);
            }
            uint32_t bh[4][4];
            const uint32_t brow = (uint32_t)(wn * 64 + (lane & 15));
#pragma unroll
            for (int u = 0; u < 4; u++) {
                uint32_t off = ((brow + u * 16) * SA) * 2 + kcol;
                ldm4(bh[u], base + OFF_BH + off);
            }
#pragma unroll
            for (int mt = 0; mt < 2; mt++)
#pragma unroll
                for (int nt = 0; nt < 8; nt++) {
                    int u = nt >> 1, p = nt & 1;
                    mma16816(acc[mt][nt], ah[mt], bh[u][p], bh[u][p + 2]);
                }
        }
    };

    ldreg(0);
    for (int it = 0; it < niter; it++) {
        const int s = it & 1;
        __syncthreads();
        store_stage(s);
        if (it + 1 < niter) ldreg(it + 1);
        __syncthreads();
        compute(s);
    }

    const int rl = lane >> 2, cl = (lane & 3) * 2;
#pragma unroll
    for (int mt = 0; mt < 2; mt++) {
#pragma unroll
        for (int g = 0; g < 2; g++) {
            const int m = row0 + wm * 32 + mt * 16 + g * 8 + rl;
#pragma unroll
            for (int nt = 0; nt < 8; nt++) {
                const int n = col0 + wn * 64 + nt * 8 + cl;
                float v0 = acc[mt][nt][2 * g];
                float v1 = acc[mt][nt][2 * g + 1];
                if (mode == 0) {
                    if (b0 && kz == 0) { v0 += b0[n]; v1 += b0[n + 1]; }
                    *(float2*)(C + (long)kz * M * N + (long)m * N + n) = make_float2(v0, v1);
                } else if (mode == 1) {
                    v0 += b0[n]; v1 += b0[n + 1];
                    v0 = 0.5f * v0 * (1.0f + erff(v0 * 0.70710678118654752f));
                    v1 = 0.5f * v1 * (1.0f + erff(v1 * 0.70710678118654752f));
                    *(float2*)(C + (long)m * N + n) = make_float2(v0, v1);
                } else { // mode 2: QKV scatter -> fp16 operand layouts
                    const int l = m >> 2, nbb = m & 3;
#pragma unroll
                    for (int q = 0; q < 2; q++) {
                        int gcol = n + q;
                        float v = q ? v1 : v0;
                        int seg = gcol / E;
                        int cc = gcol - seg * E;
                        int hh = cc >> 6, dd = cc & 63;
                        if (seg == 0) {
                            __half hb, lb;
                            split1((v + b0[cc]) * 0.125f, hb, lb);
                            long idx = (((long)(nbb * H + hh)) * L_SEQ + l) * HD + dd;
                            g_qh[idx] = hb; g_ql[idx] = lb;
                        } else if (seg == 1) {
                            long idx = (((long)(nbb * H + hh)) * L_SEQ + l) * HD + dd;
                            g_kh[idx] = __float2half(v + b1[cc]);
                        } else {
                            long idx = (((long)(nbb * H + hh)) * HD + dd) * L_SEQ + l;
                            g_vTh[idx] = __float2half(v + b2[cc]);
                        }
                    }
                }
            }
        }
    }
}

// ======= pre-split fp16 batched GEMM (attention): A hi/lo × B single ======
template<int TM, int TN, int NWM, int MODE>
__global__ void __launch_bounds__(256, 1) pgemm(
    const __half* __restrict__ Ah, const __half* __restrict__ Al,
    const __half* __restrict__ Bh,
    float* __restrict__ C, int K, long sA, long sB)
{
    constexpr int TILE_A = TM * SA * 2;
    constexpr int TILE_B = TN * SA * 2;
    constexpr int STG = 2 * TILE_A + TILE_B;
    constexpr int O_AH = 0, O_AL = TILE_A, O_BH = 2 * TILE_A;

    extern __shared__ char smem[];
    const uint32_t sb = smem_u32(smem);
    const int tid = threadIdx.x;
    const int lane = tid & 31, wid = tid >> 5;
    const int wm = wid % NWM, wn = wid / NWM;
    const int row0 = blockIdx.y * TM, col0 = blockIdx.x * TN;
    const int bz = blockIdx.z;

    const __half* pAh = Ah + (long)bz * sA;
    const __half* pAl = Al + (long)bz * sA;
    const __half* pBh = Bh + (long)bz * sB;

    float acc[2][8][4];
#pragma unroll
    for (int i = 0; i < 2; i++)
#pragma unroll
        for (int j = 0; j < 8; j++)
#pragma unroll
            for (int r = 0; r < 4; r++) acc[i][j][r] = 0.f;

    const int niter = K >> 5;

    auto load = [&](int it, int s) {
        const int koff = it * 32;
        for (int e = tid; e < TM * 4; e += 256) {
            int rr = e >> 2, cc = e & 3;
            uint32_t off = (uint32_t)((rr * SA + cc * 8) * 2);
            long go = (long)(row0 + rr) * K + koff + cc * 8;
            cp16(sb + (uint32_t)(s * STG) + O_AH + off, pAh + go);
            cp16(sb + (uint32_t)(s * STG) + O_AL + off, pAl + go);
        }
        for (int e = tid; e < TN * 4; e += 256) {
            int rr = e >> 2, cc = e & 3;
            uint32_t off = (uint32_t)((rr * SA + cc * 8) * 2);
            long go = (long)(col0 + rr) * K + koff + cc * 8;
            cp16(sb + (uint32_t)(s * STG) + O_BH + off, pBh + go);
        }
        asm volatile("cp.async.commit_group;" ::: "memory");
    };
    auto compute = [&](int s) {
        const uint32_t base = sb + (uint32_t)(s * STG);
#pragma unroll
        for (int ks = 0; ks < 2; ks++) {
            const uint32_t kcol = (uint32_t)((ks * 16 + (lane >> 4) * 8) * 2);
            uint32_t ah[2][4], al[2][4];
            const uint32_t arow = (uint32_t)(wm * 32 + (lane & 15));
#pragma unroll
            for (int t = 0; t < 2; t++) {
                uint32_t off = ((arow + t * 16) * SA) * 2 + kcol;
                ldm4(ah[t], base + O_AH + off);
                ldm4(al[t], base + O_AL + off);
            }
            uint32_t bh[4][4];
            const uint32_t brow = (uint32_t)(wn * 64 + (lane & 15));
#pragma unroll
            for (int u = 0; u < 4; u++) {
                uint32_t off = ((brow + u * 16) * SA) * 2 + kcol;
                ldm4(bh[u], base + O_BH + off);
            }
#pragma unroll
            for (int mt = 0; mt < 2; mt++)
#pragma unroll
                for (int nt = 0; nt < 8; nt++) {
                    int u = nt >> 1, p = nt & 1;
                    mma16816(acc[mt][nt], ah[mt], bh[u][p], bh[u][p + 2]);
                    mma16816(acc[mt][nt], al[mt], bh[u][p], bh[u][p + 2]);
                }
        }
    };

    load(0, 0);
    for (int it = 0; it < niter; it++) {
        if (it + 1 < niter) {
            load(it + 1, (it + 1) & 1);
            asm volatile("cp.async.wait_group 1;" ::: "memory");
        } else {
            asm volatile("cp.async.wait_group 0;" ::: "memory");
        }
        __syncthreads();
        compute(it & 1);
        __syncthreads();
    }

    const int rl = lane >> 2, cl = (lane & 3) * 2;
#pragma unroll
    for (int mt = 0; mt < 2; mt++) {
#pragma unroll
        for (int g = 0; g < 2; g++) {
            const int m = row0 + wm * 32 + mt * 16 + g * 8 + rl;
#pragma unroll
            for (int nt = 0; nt < 8; nt++) {
                const int n = col0 + wn * 64 + nt * 8 + cl;
                float v0 = acc[mt][nt][2 * g];
                float v1 = acc[mt][nt][2 * g + 1];
                if (MODE == 0) {
                    *(float2*)(C + (long)bz * L_SEQ * L_SEQ + (long)m * L_SEQ + n) =
                        make_float2(v0, v1);
                } else {
                    const int nb = bz / H, hh = bz % H;
                    *(float2*)(C + ((long)m * NB + nb) * E + hh * HD + n) =
                        make_float2(v0, v1);
                }
            }
        }
    }
}

// ---- qp[n,h,i,c] = sum_d q[n,h,i,d]*p_w[h*64+d,c]; qb = q . p_b ---------
__global__ void qp2_kernel(const float* __restrict__ p_w, const float* __restrict__ p_b)
{
    const int h = blockIdx.y;
    const int m0 = blockIdx.x * 64;
    __shared__ float w[64][65];
    __shared__ float qs[64][65];
    __shared__ float pb[64];
    const int tid = threadIdx.x;          // 256
    for (int e = tid; e < 4096; e += 256) {
        int d = e >> 6, c = e & 63;
        w[d][c] = p_w[(h * 64 + d) * 64 + c];
    }
    if (tid < 64) pb[tid] = p_b[h * 64 + tid];
    for (int e = tid; e < 4096; e += 256) {
        int r = e >> 6, d = e & 63;
        int mg = m0 + r;
        int n = mg >> 8, l = mg & 255;
        long idx = (((long)(n * H + h)) * L_SEQ + l) * HD + d;
        qs[r][d] = __half2float(g_qh[idx]) + __half2float(g_ql[idx]);
    }
    __syncthreads();

    const int rr = tid >> 2, cg = tid & 3;
    float acc[16];
#pragma unroll
    for (int c = 0; c < 16; c++) acc[c] = 0.f;
#pragma unroll
    for (int d = 0; d < 64; d++) {
        float qv = qs[rr][d];
#pragma unroll
        for (int c = 0; c < 16; c++) acc[c] += qv * w[d][cg * 16 + c];
    }
    const int mg = m0 + rr;
    const int n = mg >> 8, l = mg & 255;
    const long base = (((long)(n * H + h)) * L_SEQ + l) * HD;
#pragma unroll
    for (int c = 0; c < 16; c++) g_qp[base + cg * 16 + c] = acc[c];
    if (cg == 0) {
        float sb = 0.f;
#pragma unroll
        for (int d = 0; d < 64; d++) sb += qs[rr][d] * pb[d];
        g_qb[((long)n * H + h) * L_SEQ + l] = sb;
    }
}

// ---- cpm: scores[n,h,i,:] += qp[n,h,i,:] @ pos[n,i,:,:]^T + qb, via MMA --
#define CSA 72   // fp16 elements per row (64 + 8 pad)
__global__ void __launch_bounds__(256) cpm_kernel(const float* __restrict__ pos)
{
    __shared__ __align__(16) __half sAh[16 * CSA];
    __shared__ __align__(16) __half sAl[16 * CSA];
    __shared__ __align__(16) __half sB[L_SEQ * CSA];
    __shared__ float qbs[12];

    const int b = blockIdx.x;            // n*L + i
    const int n = b >> 8, i = b & 255;
    const int tid = threadIdx.x;
    const int lane = tid & 31, wid = tid >> 5;

    // A: qp rows (12 heads x 64), rows 12-15 zero
    for (int e = tid; e < 1024; e += 256) {
        int h = e >> 6, c = e & 63;
        float v = (h < 12) ? g_qp[(((long)(n * H + h)) * L_SEQ + i) * HD + c] : 0.f;
        __half hb, lb;
        split1(v, hb, lb);
        sAh[h * CSA + c] = hb;
        sAl[h * CSA + c] = lb;
    }
    if (tid < 12) qbs[tid] = g_qb[((long)n * H + tid) * L_SEQ + i];

    // B: pos[n,i,:,:] 256x64 fp32, coalesced float4 loads (low unroll: keep regs down)
    const float4* pr = (const float4*)(pos + (((long)n * L_SEQ + i) * L_SEQ) * 64);
#pragma unroll 4
    for (int u = 0; u < 16; u++) {
        int e = tid + u * 256;           // 0..4095
        int rr = e >> 4, cc = e & 15;
        float4 v = pr[e];
        uint2 h;
        pack4(v, h);
        *(uint2*)&sB[rr * CSA + cc * 4] = h;
    }
    __syncthreads();

    const uint32_t aB = smem_u32(sAh), aL = smem_u32(sAl), bB = smem_u32(sB);
    const int n0 = wid * 32;             // warp's j-range

    float acc[4][4];
#pragma unroll
    for (int j = 0; j < 4; j++)
#pragma unroll
        for (int r = 0; r < 4; r++) acc[j][r] = 0.f;

#pragma unroll
    for (int ks = 0; ks < 4; ks++) {
        const uint32_t kcol = (uint32_t)((ks * 16 + (lane >> 4) * 8) * 2);
        uint32_t ah[4], al[4];
        {
            uint32_t off = ((uint32_t)(lane & 15) * CSA) * 2 + kcol;
            ldm4(ah, aB + off);
            ldm4(al, aL + off);
        }
        uint32_t bh[2][4];
#pragma unroll
        for (int t = 0; t < 2; t++) {
            uint32_t off = ((uint32_t)(n0 + (lane & 15) + t * 16) * CSA) * 2 + kcol;
            ldm4(bh[t], bB + off);
        }
#pragma unroll
        for (int nt = 0; nt < 4; nt++) {
            int u = nt >> 1, p = nt & 1;
            mma16816(acc[nt], ah, bh[u][p], bh[u][p + 2]);
            mma16816(acc[nt], al, bh[u][p], bh[u][p + 2]);
        }
    }

    // epilogue: rows 0..11 -> scores += (RMW)
    const int rl = lane >> 2, cl = (lane & 3) * 2;
#pragma unroll
    for (int g = 0; g < 2; g++) {
        const int m = g * 8 + rl;
        if (m < 12) {
            const float qb = qbs[m];
            float* srow = g_scores + ((((long)n * H + m) * L_SEQ + i) * L_SEQ);
#pragma unroll
            for (int nt = 0; nt < 4; nt++) {
                const int j = n0 + nt * 8 + cl;
                float2 old = *(float2*)(srow + j);
                old.x += acc[nt][2 * g] + qb;
                old.y += acc[nt][2 * g + 1] + qb;
                *(float2*)(srow + j) = old;
            }
        }
    }
}

// ---- row softmax over last dim (256); writes probs as fp16 hi/lo --------
__global__ void softmax_kernel()
{
    const long row = blockIdx.x;
    const int j = threadIdx.x;
    __shared__ float red[8];
    float x = g_scores[row * L_SEQ + j];
    float m = x;
#pragma unroll
    for (int o = 16; o > 0; o >>= 1) m = fmaxf(m, __shfl_xor_sync(0xffffffffu, m, o));
    if ((j & 31) == 0) red[j >> 5] = m;
    __syncthreads();
    if (j < 32) {
        float t = (j < 8) ? red[j] : -1e30f;
#pragma unroll
        for (int o = 4; o > 0; o >>= 1) t = fmaxf(t, __shfl_xor_sync(0xffffffffu, t, o));
        if (j == 0) red[0] = t;
    }
    __syncthreads();
    m = red[0];
    float e = __expf(x - m);
    float s = e;
#pragma unroll
    for (int o = 16; o > 0; o >>= 1) s += __shfl_xor_sync(0xffffffffu, s, o);
    __syncthreads();
    if ((j & 31) == 0) red[j >> 5] = s;
    __syncthreads();
    if (j < 32) {
        float t = (j < 8) ? red[j] : 0.f;
#pragma unroll
        for (int o = 4; o > 0; o >>= 1) t += __shfl_xor_sync(0xffffffffu, t, o);
        if (j == 0) red[0] = t;
    }
    __syncthreads();
    float p = e / red[0];
    __half hb, lb;
    split1(p, hb, lb);
    g_ph[row * L_SEQ + j] = hb;
    g_pl[row * L_SEQ + j] = lb;
}

// ---- out = LayerNorm(a + sum_{z<np} p[z*ps + .]) * gamma + beta ---------
__global__ void ln_multi(const float* __restrict__ a, const float* __restrict__ p,
                         int nparts, long pstride,
                         const float* __restrict__ gamma, const float* __restrict__ beta,
                         float* __restrict__ out)
{
    const int row = blockIdx.x;
    const int t = threadIdx.x;
    __shared__ float rs[8], rq[8];
    float v[3];
    float s = 0.f, s2 = 0.f;
#pragma unroll
    for (int u = 0; u < 3; u++) {
        long idx = (long)row * E + t + u * 256;
        float x = a[idx];
        for (int z = 0; z < nparts; z++) x += p[z * pstride + idx];
        v[u] = x; s += x; s2 += x * x;
    }
#pragma unroll
    for (int o = 16; o > 0; o >>= 1) {
        s  += __shfl_xor_sync(0xffffffffu, s, o);
        s2 += __shfl_xor_sync(0xffffffffu, s2, o);
    }
    if ((t & 31) == 0) { rs[t >> 5] = s; rq[t >> 5] = s2; }
    __syncthreads();
    if (t < 32) {
        float a1 = (t < 8) ? rs[t] : 0.f;
        float a2 = (t < 8) ? rq[t] : 0.f;
#pragma unroll
        for (int o = 4; o > 0; o >>= 1) {
            a1 += __shfl_xor_sync(0xffffffffu, a1, o);
            a2 += __shfl_xor_sync(0xffffffffu, a2, o);
        }
        if (t == 0) { rs[0] = a1; rq[0] = a2; }
    }
    __syncthreads();
    float mean = rs[0] * (1.f / 768.f);
    float var  = rq[0] * (1.f / 768.f) - mean * mean;
    float r = rsqrtf(var + 1e-5f);
#pragma unroll
    for (int u = 0; u < 3; u++) {
        int c = t + u * 256;
        out[(long)row * E + c] = (v[u] - mean) * r * gamma[c] + beta[c];
    }
}

// =================== host launcher ===================
extern "C" void kernel_launch(void* const* d_in, const int* in_sizes, int n_in,
                              void* d_out, int out_size)
{
    const float* src    = (const float*)d_in[0];
    const float* pos    = (const float*)d_in[1];
    const float* q_w    = (const float*)d_in[2];
    const float* q_b    = (const float*)d_in[3];
    const float* k_w    = (const float*)d_in[4];
    const float* k_b    = (const float*)d_in[5];
    const float* v_w    = (const float*)d_in[6];
    const float* v_b    = (const float*)d_in[7];
    const float* p_w    = (const float*)d_in[8];
    const float* p_b    = (const float*)d_in[9];
    const float* out_w  = (const float*)d_in[10];
    const float* out_b  = (const float*)d_in[11];
    const float* lin1_w = (const float*)d_in[12];
    const float* lin1_b = (const float*)d_in[13];
    const float* lin2_w = (const float*)d_in[14];
    const float* lin2_b = (const float*)d_in[15];
    const float* n1_g   = (const float*)d_in[16];
    const float* n1_b   = (const float*)d_in[17];
    const float* n2_g   = (const float*)d_in[18];
    const float* n2_b   = (const float*)d_in[19];
    float* out = (float*)d_out;

    auto pg_scores = pgemm<128, 128, 4, 0>;
    auto pg_ctx    = pgemm<256, 64, 8, 1>;
    const int smem_scores = 2 * (2 * 128 * SA * 2 + 128 * SA * 2);          // 61440
    const int smem_ctx    = 2 * (2 * 256 * SA * 2 + 64 * SA * 2);           // 92160
    cudaFuncSetAttribute(tgemm, cudaFuncAttributeMaxDynamicSharedMemorySize, SM_TOTAL);
    cudaFuncSetAttribute(pg_scores, cudaFuncAttributeMaxDynamicSharedMemorySize, smem_scores);
    cudaFuncSetAttribute(pg_ctx, cudaFuncAttributeMaxDynamicSharedMemorySize, smem_ctx);

    float *pscores, *pctx, *pattn, *px1, *pff1, *pff2;
    cudaGetSymbolAddress((void**)&pscores, g_scores);
    cudaGetSymbolAddress((void**)&pctx,    g_ctx);
    cudaGetSymbolAddress((void**)&pattn,   g_attnout);
    cudaGetSymbolAddress((void**)&px1,     g_x1);
    cudaGetSymbolAddress((void**)&pff1,    g_ff1);
    cudaGetSymbolAddress((void**)&pff2,    g_ff2);

    __half *qh, *ql, *kh, *vTh, *ph, *pl;
    cudaGetSymbolAddress((void**)&qh,  g_qh);  cudaGetSymbolAddress((void**)&ql,  g_ql);
    cudaGetSymbolAddress((void**)&kh,  g_kh);
    cudaGetSymbolAddress((void**)&vTh, g_vTh);
    cudaGetSymbolAddress((void**)&ph,  g_ph);  cudaGetSymbolAddress((void**)&pl,  g_pl);

    // ---- fused QKV projection, epilogue writes fp16 operand layouts ----
    tgemm<<<dim3(3 * E / 128, NTOK / 128, 1), 256, SM_TOTAL>>>(
        src, q_w, k_w, v_w, q_b, k_b, v_b,
        nullptr, NTOK, 3 * E, E, E, 2);

    // ---- attention ----
    qp2_kernel<<<dim3(16, 12), 256>>>(p_w, p_b);
    pg_scores<<<dim3(2, 2, NHB), 256, smem_scores>>>(
        qh, ql, kh, pscores, HD, (long)L_SEQ * HD, (long)L_SEQ * HD);
    cpm_kernel<<<NB * L_SEQ, 256>>>(pos);
    softmax_kernel<<<NB * H * L_SEQ, 256>>>();
    pg_ctx<<<dim3(1, 1, NHB), 256, smem_ctx>>>(
        ph, pl, vTh, pctx, L_SEQ, (long)L_SEQ * L_SEQ, (long)HD * L_SEQ);

    // ---- output projection (split-K=2) ----
    tgemm<<<dim3(E / 128, NTOK / 128, 2), 256, SM_TOTAL>>>(
        pctx, out_w, nullptr, nullptr, out_b, nullptr, nullptr,
        pattn, NTOK, E, E, E / 2, 0);

    // ---- x1 = LN(src + partials) ----
    ln_multi<<<NTOK, 256>>>(src, pattn, 2, (long)NTOK * E, n1_g, n1_b, px1);

    // ---- FFN ----
    tgemm<<<dim3(FF / 128, NTOK / 128, 1), 256, SM_TOTAL>>>(
        px1, lin1_w, nullptr, nullptr, lin1_b, nullptr, nullptr,
        pff1, NTOK, FF, E, E, 1);
    tgemm<<<dim3(E / 128, NTOK / 128, 4), 256, SM_TOTAL>>>(
        pff1, lin2_w, nullptr, nullptr, lin2_b, nullptr, nullptr,
        pff2, NTOK, E, FF, FF / 4, 0);

    // ---- out = LN(x1 + 4 partials) ----
    ln_multi<<<NTOK, 256>>>(px1, pff2, 4, (long)NTOK * E, n2_g, n2_b, out);
}